// round 8
// baseline (speedup 1.0000x reference)
#include <cuda_runtime.h>
#include <cuda_bf16.h>
#include <cstdint>
#include <cstring>

#define BN 2
#define CIN 64
#define HH 256
#define WW 256
#define KK 9
#define OC1 10
#define HW (HH*WW)

// ---------------- scratch ----------------
__device__ float g_off[BN*OC1*HW];
__device__ float g_offpart[BN*256*20];
__device__ float g_offstats[BN*5*2];
// w tiles: [split][k][chunk][64 co x 16 ci], 48B rows, 3072B per tile
__device__ __align__(16) unsigned char g_wb2[2*KK*4*3072];
__device__ float g_part[BN*512*16*2];
__device__ float g_outmr[BN*16*2];

// ---------------- helpers ----------------
__device__ __forceinline__ uint32_t smem_u32(const void* p) {
    uint32_t a;
    asm("{ .reg .u64 t; cvta.to.shared.u64 t, %1; cvt.u32.u64 %0, t; }" : "=r"(a) : "l"(p));
    return a;
}
__device__ __forceinline__ void ldsm_x4(uint32_t* r, uint32_t addr) {
    asm volatile("ldmatrix.sync.aligned.m8n8.x4.shared.b16 {%0,%1,%2,%3}, [%4];"
                 : "=r"(r[0]), "=r"(r[1]), "=r"(r[2]), "=r"(r[3]) : "r"(addr));
}
__device__ __forceinline__ void ldsm_x2(uint32_t* r, uint32_t addr) {
    asm volatile("ldmatrix.sync.aligned.m8n8.x2.shared.b16 {%0,%1}, [%2];"
                 : "=r"(r[0]), "=r"(r[1]) : "r"(addr));
}
__device__ __forceinline__ void mma16816(float* d, const uint32_t* a, const uint32_t* b) {
    asm volatile("mma.sync.aligned.m16n8k16.row.col.f32.bf16.bf16.f32 "
                 "{%0,%1,%2,%3}, {%4,%5,%6,%7}, {%8,%9}, {%0,%1,%2,%3};"
                 : "+f"(d[0]), "+f"(d[1]), "+f"(d[2]), "+f"(d[3])
                 : "r"(a[0]), "r"(a[1]), "r"(a[2]), "r"(a[3]), "r"(b[0]), "r"(b[1]));
}
__device__ __forceinline__ void cpasync16(uint32_t saddr, const void* gptr) {
    asm volatile("cp.async.ca.shared.global [%0], [%1], 16;" :: "r"(saddr), "l"(gptr) : "memory");
}

// smem layout
#define OFF_RB    0          // rowbuffer: 16 ci x 10 rows x 136 cols fp32 (87040 B)
#define OFF_SHI   87040      // S tile [128 pix][16 ci] bf16, 48B rows (6144 B)
#define OFF_SLO   93184
#define OFF_WHI   99328      // W tile [64 co][16 ci] bf16, 48B rows (3072 B)
#define OFF_WLO   102400
#define OFF_IY    105472     // 9*128 floats
#define OFF_SUMS  110080     // 32 floats
#define SMEM_BYTES 110208

// ---------------- kernel 1: 3x3 conv, 64 -> 10 channels (+ GN stat partials) ----------------
__global__ void conv1_kernel(const float* __restrict__ x,
                             const float* __restrict__ w,
                             const float* __restrict__ bias) {
    int b = blockIdx.z, w0 = blockIdx.x * 32, h0 = blockIdx.y * 8;
    int t = threadIdx.x;
    int tw = t & 31, th = t >> 5;
    __shared__ float xs[10][34];
    __shared__ float ws[OC1][9];
    __shared__ float red[8][20];
    float acc[OC1];
#pragma unroll
    for (int o = 0; o < OC1; o++) acc[o] = 0.f;

    for (int ci = 0; ci < CIN; ci++) {
        for (int i = t; i < 340; i += 256) {
            int r = i / 34, c = i % 34;
            int hy = h0 - 1 + r, wx = w0 - 1 + c;
            float v = 0.f;
            if (hy >= 0 && hy < HH && wx >= 0 && wx < WW)
                v = x[((size_t)(b*CIN + ci)*HH + hy)*WW + wx];
            xs[r][c] = v;
        }
        if (t < OC1*9) ws[t/9][t%9] = w[(t/9)*CIN*9 + ci*9 + (t%9)];
        __syncthreads();

        float xv[9];
#pragma unroll
        for (int dy = 0; dy < 3; dy++)
#pragma unroll
            for (int dx = 0; dx < 3; dx++)
                xv[dy*3+dx] = xs[th+dy][tw+dx];
#pragma unroll
        for (int o = 0; o < OC1; o++) {
            float a = acc[o];
#pragma unroll
            for (int tp = 0; tp < 9; tp++) a = fmaf(ws[o][tp], xv[tp], a);
            acc[o] = a;
        }
        __syncthreads();
    }
    int lane = t & 31, wid = t >> 5;
#pragma unroll
    for (int o = 0; o < OC1; o++) {
        float v = acc[o] + bias[o];
        g_off[((size_t)(b*OC1 + o)*HH + h0 + th)*WW + w0 + tw] = v;
        float s = v, q = v*v;
#pragma unroll
        for (int m = 16; m; m >>= 1) {
            s += __shfl_xor_sync(0xffffffff, s, m);
            q += __shfl_xor_sync(0xffffffff, q, m);
        }
        if (lane == 0) { red[wid][o*2] = s; red[wid][o*2+1] = q; }
    }
    __syncthreads();
    if (t < 20) {
        float a = 0.f;
#pragma unroll
        for (int wq = 0; wq < 8; wq++) a += red[wq][t];
        int blk = blockIdx.x + 8*blockIdx.y;
        g_offpart[((size_t)(b*256) + blk)*20 + t] = a;
    }
}

// ---------------- kernel 2: reduce offset GN partials ----------------
__global__ void offstats_kernel() {
    int b = blockIdx.x / 5, g = blockIdx.x % 5;
    int t = threadIdx.x;
    float s = 0.f, q = 0.f;
    for (int i = t; i < 256; i += 256) {
        const float* p = g_offpart + ((size_t)(b*256) + i)*20;
        s += p[(2*g)*2]   + p[(2*g+1)*2];
        q += p[(2*g)*2+1] + p[(2*g+1)*2+1];
    }
    __shared__ float rs[256], rq[256];
    rs[t] = s; rq[t] = q; __syncthreads();
    for (int o = 128; o > 0; o >>= 1) {
        if (t < o) { rs[t] += rs[t+o]; rq[t] += rq[t+o]; }
        __syncthreads();
    }
    if (t == 0) {
        float n = (float)(2*HW);
        float mean = rs[0] / n;
        float var = rq[0] / n - mean*mean;
        g_offstats[(b*5+g)*2]   = mean;
        g_offstats[(b*5+g)*2+1] = rsqrtf(var + 1e-5f);
    }
}

// ---------------- kernel 3: split w_dsc into bf16 hi/lo, [k][chunk] 48B-row tiles ----------------
__global__ void wprep_kernel(const float* __restrict__ wdsc) {
    int lin = blockIdx.x*256 + threadIdx.x;       // 9*64*64
    if (lin >= KK*64*64) return;
    int ci = lin & 63, co = (lin >> 6) & 63, k = lin >> 12;
    float v = wdsc[((size_t)(co*64 + ci))*KK + k];
    __nv_bfloat16 hi = __float2bfloat16(v);
    __nv_bfloat16 lo = __float2bfloat16(v - __bfloat162float(hi));
    int chunk = ci >> 4, cil = ci & 15;
    size_t off = (size_t)(k*4 + chunk)*3072 + co*48 + ((cil >> 3) << 4) + ((cil & 7) << 1);
    *(__nv_bfloat16*)(g_wb2 + off) = hi;
    *(__nv_bfloat16*)(g_wb2 + off + (size_t)2*KK*4*3072/2) = lo;   // +110592
}

// ---------------- kernel 4: rowbuffered sampling + mma.sync GEMM ----------------
// CTA: 128 pixels x 64 co. Outer: 4 ci-chunks (16 ci); inner: 9 taps. 2 CTAs/SM.
__global__ void __launch_bounds__(256, 2)
main_kernel(const float* __restrict__ x,
            const float* __restrict__ gno_w, const float* __restrict__ gno_b,
            const float* __restrict__ b_dsc,
            float* __restrict__ out) {
    extern __shared__ __align__(16) char smem[];
    uint32_t sb = smem_u32(smem);
    float* rbf   = (float*)(smem + OFF_RB);
    float* iy_sh = (float*)(smem + OFF_IY);
    float* sums  = (float*)(smem + OFF_SUMS);

    int t = threadIdx.x, lane = t & 31, wid = t >> 5;
    int b = blockIdx.z, h = blockIdx.y, w0 = blockIdx.x * 128;
    if (t < 32) sums[t] = 0.f;

    // Phase 0: GN+tanh, outward cumsum, clamped iy
    if (t < 128) {
        int p = t, wg = w0 + p;
        float v[9];
#pragma unroll
        for (int c = 0; c < 9; c++) {
            float raw = g_off[((size_t)(b*OC1 + c)*HH + h)*WW + wg];
            int g = c >> 1;
            float mean = g_offstats[(b*5+g)*2];
            float rstd = g_offstats[(b*5+g)*2+1];
            v[c] = tanhf((raw - mean)*rstd*gno_w[c] + gno_b[c]);
        }
        float cum[9];
        cum[4] = 0.f;
        cum[3] = v[3]; cum[2] = cum[3]+v[2]; cum[1] = cum[2]+v[1]; cum[0] = cum[1]+v[0];
        cum[5] = v[5]; cum[6] = cum[5]+v[6]; cum[7] = cum[6]+v[7]; cum[8] = cum[7]+v[8];
#pragma unroll
        for (int k = 0; k < 9; k++)
            iy_sh[k*128 + p] = fminf(fmaxf((float)h + cum[k], 0.f), 255.f);
    }

    const float* xb = x + (size_t)b*CIN*HW;
    int pixw = (wid & 3)*32 + lane;      // pixel this thread samples
    int cihalf = (wid >> 2)*8;           // 8-ci half within chunk

    int wm = wid & 1, wn = wid >> 1;
    float acc[2][4][4];
#pragma unroll
    for (int i = 0; i < 2; i++)
#pragma unroll
        for (int j = 0; j < 4; j++)
#pragma unroll
            for (int l = 0; l < 4; l++) acc[i][j][l] = 0.f;

    for (int chunk = 0; chunk < 4; chunk++) {
        // ---- rowbuffer load: 16 ci x 10 rows x 136 cols, coalesced (2 ci per warp) ----
#pragma unroll
        for (int j = 0; j < 2; j++) {
            int cil = wid*2 + j;
            const float* xc = xb + (size_t)(chunk*16 + cil)*HW;
            float* dstc = rbf + cil*1360;
#pragma unroll
            for (int rr = 0; rr < 10; rr++) {
                int ry = min(max(h - 4 + rr, 0), HH - 1);
                const float* src = xc + (size_t)ry*WW;
                float* dst = dstc + rr*136;
                for (int cc = lane; cc < 136; cc += 32) {
                    int cx = min(max(w0 - 4 + cc, 0), WW - 1);
                    dst[cc] = __ldg(src + cx);
                }
            }
        }
        __syncthreads();   // rowbuffer ready (also: iy_sh ready on first pass)

        for (int k = 0; k < KK; k++) {
            // ---- async W tile copy ----
            {
                const unsigned char* wsrc = g_wb2 + (size_t)(k*4 + chunk)*3072;
                if (t < 192) {
                    cpasync16(sb + OFF_WHI + t*16, wsrc + t*16);
                    cpasync16(sb + OFF_WLO + t*16, wsrc + 110592 + t*16);
                }
                asm volatile("cp.async.commit_group;" ::: "memory");
            }

            // ---- sample 8 ci for pixel pixw from rowbuffer ----
            float iy = iy_sh[k*128 + pixw];
            float y0f = floorf(iy);
            float wy = iy - y0f;
            int y0 = (int)y0f;
            int rr0 = y0 - h + 4;
            int rr1 = min(y0 + 1, HH - 1) - h + 4;
            int cc = min(max(w0 + pixw + k - 4, 0), WW - 1) - w0 + 4;
            int base0 = rr0*136 + cc, base1 = rr1*136 + cc;

            float v[8];
#pragma unroll
            for (int j = 0; j < 8; j++) {
                const float* pci = rbf + (cihalf + j)*1360;
                float a = pci[base0], c = pci[base1];
                v[j] = fmaf(c - a, wy, a);
            }
            uint32_t hp[4], lp[4];
#pragma unroll
            for (int j = 0; j < 4; j++) {
                __nv_bfloat162 h2 = __floats2bfloat162_rn(v[2*j], v[2*j+1]);
                float2 hf = __bfloat1622float2(h2);
                __nv_bfloat162 l2 = __floats2bfloat162_rn(v[2*j] - hf.x, v[2*j+1] - hf.y);
                memcpy(&hp[j], &h2, 4);
                memcpy(&lp[j], &l2, 4);
            }
            uint32_t soff = (uint32_t)(pixw*48 + (cihalf >> 3)*16);
            *(uint4*)(smem + OFF_SHI + soff) = make_uint4(hp[0], hp[1], hp[2], hp[3]);
            *(uint4*)(smem + OFF_SLO + soff) = make_uint4(lp[0], lp[1], lp[2], lp[3]);

            asm volatile("cp.async.wait_group 0;" ::: "memory");
            __syncthreads();   // S + W ready

            // ---- one k16 mma step ----
            uint32_t ahi[2][4], alo[2][4];
#pragma unroll
            for (int mt = 0; mt < 2; mt++) {
                uint32_t row = (uint32_t)(wm*32 + mt*16 + (lane & 15));
                uint32_t a_off = row*48 + (lane >> 4)*16;
                ldsm_x4(ahi[mt], sb + OFF_WHI + a_off);
                ldsm_x4(alo[mt], sb + OFF_WLO + a_off);
            }
            uint32_t bhi[4][2], blo[4][2];
#pragma unroll
            for (int nt = 0; nt < 4; nt++) {
                uint32_t row = (uint32_t)(wn*32 + nt*8 + (lane & 7));
                uint32_t b_off = row*48 + ((lane >> 3) & 1)*16;
                ldsm_x2(bhi[nt], sb + OFF_SHI + b_off);
                ldsm_x2(blo[nt], sb + OFF_SLO + b_off);
            }
#pragma unroll
            for (int mt = 0; mt < 2; mt++)
#pragma unroll
                for (int nt = 0; nt < 4; nt++) {
                    mma16816(acc[mt][nt], ahi[mt], bhi[nt]);
                    mma16816(acc[mt][nt], alo[mt], bhi[nt]);
                    mma16816(acc[mt][nt], ahi[mt], blo[nt]);
                }
            __syncthreads();   // mma done; S (and on k=8, rowbuffer) free
        }
    }

    // ---- epilogue: bias, store, GN partial sums ----
    {
        int q = lane >> 2;
        int pp = (lane & 3) * 2;
        float s_l[2][2] = {{0.f,0.f},{0.f,0.f}}, q_l[2][2] = {{0.f,0.f},{0.f,0.f}};
#pragma unroll
        for (int mt = 0; mt < 2; mt++) {
            int cog = wm*32 + mt*16 + q;
            float b0 = __ldg(b_dsc + cog);
            float b1 = __ldg(b_dsc + cog + 8);
#pragma unroll
            for (int nt = 0; nt < 4; nt++) {
                int pix = wn*32 + nt*8 + pp;
                float v0 = acc[mt][nt][0] + b0;
                float v1 = acc[mt][nt][1] + b0;
                float v2 = acc[mt][nt][2] + b1;
                float v3 = acc[mt][nt][3] + b1;
                *(float2*)&out[((size_t)(b*64 + cog)*HH + h)*WW + w0 + pix]     = make_float2(v0, v1);
                *(float2*)&out[((size_t)(b*64 + cog + 8)*HH + h)*WW + w0 + pix] = make_float2(v2, v3);
                s_l[mt][0] += v0 + v1; q_l[mt][0] += v0*v0 + v1*v1;
                s_l[mt][1] += v2 + v3; q_l[mt][1] += v2*v2 + v3*v3;
            }
        }
#pragma unroll
        for (int mt = 0; mt < 2; mt++)
#pragma unroll
            for (int hf = 0; hf < 2; hf++) {
#pragma unroll
                for (int m = 1; m <= 2; m <<= 1) {
                    s_l[mt][hf] += __shfl_xor_sync(0xffffffff, s_l[mt][hf], m);
                    q_l[mt][hf] += __shfl_xor_sync(0xffffffff, q_l[mt][hf], m);
                }
                if ((lane & 3) == 0) {
                    int grp = (wm*32 + mt*16 + hf*8 + q) >> 2;
                    atomicAdd(&sums[2*grp],   s_l[mt][hf]);
                    atomicAdd(&sums[2*grp+1], q_l[mt][hf]);
                }
            }
    }
    __syncthreads();
    if (t < 32) {
        int bw = blockIdx.x + 2*h;
        g_part[((size_t)(b*512 + bw)*16 + (t >> 1))*2 + (t & 1)] = sums[t];
    }
}

// ---------------- kernel 5: reduce out-GN partials ----------------
__global__ void outstats_kernel() {
    int b = blockIdx.x >> 4, g = blockIdx.x & 15;
    int t = threadIdx.x;
    float s = 0.f, q = 0.f;
    for (int i = t; i < 512; i += 256) {
        size_t idx = ((size_t)(b*512 + i)*16 + g)*2;
        s += g_part[idx];
        q += g_part[idx + 1];
    }
    __shared__ float rs[256], rq[256];
    rs[t] = s; rq[t] = q; __syncthreads();
    for (int o = 128; o > 0; o >>= 1) {
        if (t < o) { rs[t] += rs[t+o]; rq[t] += rq[t+o]; }
        __syncthreads();
    }
    if (t == 0) {
        float n = 4.f * HW;
        float mean = rs[0] / n;
        float var = rq[0] / n - mean*mean;
        g_outmr[(b*16+g)*2]   = mean;
        g_outmr[(b*16+g)*2+1] = rsqrtf(var + 1e-5f);
    }
}

// ---------------- kernel 6: apply GN + ReLU ----------------
__global__ void apply_kernel(float* __restrict__ out,
                             const float* __restrict__ gn_w,
                             const float* __restrict__ gn_b) {
    int idx4 = blockIdx.x*blockDim.x + threadIdx.x;
    size_t base = (size_t)idx4 * 4;
    int co = (int)((base >> 16) & 63);
    int b  = (int)(base >> 22);
    int g  = co >> 2;
    float mean = g_outmr[(b*16+g)*2];
    float rstd = g_outmr[(b*16+g)*2+1];
    float sc = rstd * gn_w[co];
    float sh = gn_b[co] - mean * sc;
    float4 v = *(float4*)&out[base];
    v.x = fmaxf(fmaf(v.x, sc, sh), 0.f);
    v.y = fmaxf(fmaf(v.y, sc, sh), 0.f);
    v.z = fmaxf(fmaf(v.z, sc, sh), 0.f);
    v.w = fmaxf(fmaf(v.w, sc, sh), 0.f);
    *(float4*)&out[base] = v;
}

// ---------------- launch ----------------
extern "C" void kernel_launch(void* const* d_in, const int* in_sizes, int n_in,
                              void* d_out, int out_size) {
    const float* x     = (const float*)d_in[0];
    const float* w_off = (const float*)d_in[1];
    const float* b_off = (const float*)d_in[2];
    const float* gno_w = (const float*)d_in[3];
    const float* gno_b = (const float*)d_in[4];
    const float* w_dsc = (const float*)d_in[5];
    const float* b_dsc = (const float*)d_in[6];
    const float* gn_w  = (const float*)d_in[7];
    const float* gn_b  = (const float*)d_in[8];
    float* out = (float*)d_out;

    cudaFuncSetAttribute(main_kernel, cudaFuncAttributeMaxDynamicSharedMemorySize, SMEM_BYTES);

    conv1_kernel<<<dim3(WW/32, HH/8, BN), 256>>>(x, w_off, b_off);
    offstats_kernel<<<BN*5, 256>>>();
    wprep_kernel<<<(KK*64*64 + 255)/256, 256>>>(w_dsc);
    main_kernel<<<dim3(2, HH, BN), 256, SMEM_BYTES>>>(x, gno_w, gno_b, b_dsc, out);
    outstats_kernel<<<BN*16, 256>>>();
    apply_kernel<<<4096, 512>>>(out, gn_w, gn_b);
}

// round 9
// speedup vs baseline: 1.9999x; 1.9999x over previous
#include <cuda_runtime.h>
#include <cuda_bf16.h>
#include <cstdint>
#include <cstring>

#define BN 2
#define CIN 64
#define HH 256
#define WW 256
#define KK 9
#define OC1 10
#define HW (HH*WW)

// ---------------- scratch ----------------
__device__ float g_off[BN*OC1*HW];
__device__ float g_offpart[BN*256*20];    // per-conv1-block (sum,sumsq) x 10 ch
__device__ float g_offstats[BN*5*2];
__device__ __align__(16) __nv_bfloat16 g_wbf[2*KK*4096];  // [split][k][swizzled 64co x 64ci]
__device__ float g_part[BN*512*16*2];
__device__ float g_outmr[BN*16*2];

// ---------------- mma helpers (baseline PTX, no 'a' features) ----------------
__device__ __forceinline__ uint32_t smem_u32(const void* p) {
    uint32_t a;
    asm("{ .reg .u64 t; cvta.to.shared.u64 t, %1; cvt.u32.u64 %0, t; }" : "=r"(a) : "l"(p));
    return a;
}
__device__ __forceinline__ void ldsm_x4(uint32_t* r, uint32_t addr) {
    asm volatile("ldmatrix.sync.aligned.m8n8.x4.shared.b16 {%0,%1,%2,%3}, [%4];"
                 : "=r"(r[0]), "=r"(r[1]), "=r"(r[2]), "=r"(r[3]) : "r"(addr));
}
__device__ __forceinline__ void ldsm_x2(uint32_t* r, uint32_t addr) {
    asm volatile("ldmatrix.sync.aligned.m8n8.x2.shared.b16 {%0,%1}, [%2];"
                 : "=r"(r[0]), "=r"(r[1]) : "r"(addr));
}
__device__ __forceinline__ void mma16816(float* d, const uint32_t* a, const uint32_t* b) {
    asm volatile("mma.sync.aligned.m16n8k16.row.col.f32.bf16.bf16.f32 "
                 "{%0,%1,%2,%3}, {%4,%5,%6,%7}, {%8,%9}, {%0,%1,%2,%3};"
                 : "+f"(d[0]), "+f"(d[1]), "+f"(d[2]), "+f"(d[3])
                 : "r"(a[0]), "r"(a[1]), "r"(a[2]), "r"(a[3]), "r"(b[0]), "r"(b[1]));
}
__device__ __forceinline__ void cpasync16(uint32_t saddr, const void* gptr) {
    asm volatile("cp.async.ca.shared.global [%0], [%1], 16;" :: "r"(saddr), "l"(gptr) : "memory");
}

// smem layout (dynamic), single stage
#define OFF_SHI  0           // [128 pix][64 ci] bf16 swizzled (16 KB)
#define OFF_SLO  16384
#define OFF_WHI  32768       // [64 co][64 ci] bf16 swizzled (8 KB)
#define OFF_WLO  40960
#define OFF_IY   49152       // 9*128 floats
#define OFF_SUMS 53760       // 32 floats
#define SMEM_BYTES 53888

// ---------------- kernel 1: 3x3 conv, 64 -> 10 channels (+ GN stat partials) ----------------
// 2 input channels per barrier pair.
__global__ void conv1_kernel(const float* __restrict__ x,
                             const float* __restrict__ w,
                             const float* __restrict__ bias) {
    int b = blockIdx.z, w0 = blockIdx.x * 32, h0 = blockIdx.y * 8;
    int t = threadIdx.x;
    int tw = t & 31, th = t >> 5;
    __shared__ float xs[2][10][34];
    __shared__ float ws[2][OC1][9];
    __shared__ float red[8][20];
    float acc[OC1];
#pragma unroll
    for (int o = 0; o < OC1; o++) acc[o] = 0.f;

    for (int ci = 0; ci < CIN; ci += 2) {
        for (int i = t; i < 680; i += 256) {
            int half = i >= 340;
            int li = half ? i - 340 : i;
            int r = li / 34, c = li % 34;
            int hy = h0 - 1 + r, wx = w0 - 1 + c;
            float v = 0.f;
            if (hy >= 0 && hy < HH && wx >= 0 && wx < WW)
                v = __ldg(&x[((size_t)(b*CIN + ci + half)*HH + hy)*WW + wx]);
            xs[half][r][c] = v;
        }
        if (t < OC1*9*2) {
            int half = t >= OC1*9;
            int li = half ? t - OC1*9 : t;
            ws[half][li/9][li%9] = __ldg(&w[(li/9)*CIN*9 + (ci + half)*9 + (li%9)]);
        }
        __syncthreads();

#pragma unroll
        for (int half = 0; half < 2; half++) {
            float xv[9];
#pragma unroll
            for (int dy = 0; dy < 3; dy++)
#pragma unroll
                for (int dx = 0; dx < 3; dx++)
                    xv[dy*3+dx] = xs[half][th+dy][tw+dx];
#pragma unroll
            for (int o = 0; o < OC1; o++) {
                float a = acc[o];
#pragma unroll
                for (int tp = 0; tp < 9; tp++) a = fmaf(ws[half][o][tp], xv[tp], a);
                acc[o] = a;
            }
        }
        __syncthreads();
    }
    int lane = t & 31, wid = t >> 5;
#pragma unroll
    for (int o = 0; o < OC1; o++) {
        float v = acc[o] + bias[o];
        g_off[((size_t)(b*OC1 + o)*HH + h0 + th)*WW + w0 + tw] = v;
        float s = v, q = v*v;
#pragma unroll
        for (int m = 16; m; m >>= 1) {
            s += __shfl_xor_sync(0xffffffff, s, m);
            q += __shfl_xor_sync(0xffffffff, q, m);
        }
        if (lane == 0) { red[wid][o*2] = s; red[wid][o*2+1] = q; }
    }
    __syncthreads();
    if (t < 20) {
        float a = 0.f;
#pragma unroll
        for (int wq = 0; wq < 8; wq++) a += red[wq][t];
        int blk = blockIdx.x + 8*blockIdx.y;   // 0..255
        g_offpart[((size_t)(b*256) + blk)*20 + t] = a;
    }
}

// ---------------- kernel 2: reduce offset GN partials ----------------
__global__ void offstats_kernel() {
    int b = blockIdx.x / 5, g = blockIdx.x % 5;
    int t = threadIdx.x;
    float s = 0.f, q = 0.f;
    for (int i = t; i < 256; i += 256) {
        const float* p = g_offpart + ((size_t)(b*256) + i)*20;
        s += p[(2*g)*2]   + p[(2*g+1)*2];
        q += p[(2*g)*2+1] + p[(2*g+1)*2+1];
    }
    __shared__ float rs[256], rq[256];
    rs[t] = s; rq[t] = q; __syncthreads();
    for (int o = 128; o > 0; o >>= 1) {
        if (t < o) { rs[t] += rs[t+o]; rq[t] += rq[t+o]; }
        __syncthreads();
    }
    if (t == 0) {
        float n = (float)(2*HW);
        float mean = rs[0] / n;
        float var = rq[0] / n - mean*mean;
        g_offstats[(b*5+g)*2]   = mean;
        g_offstats[(b*5+g)*2+1] = rsqrtf(var + 1e-5f);
    }
}

// ---------------- kernel 3: split w_dsc into bf16 hi/lo, [k][co][ci] swizzled ----------------
__global__ void wprep_kernel(const float* __restrict__ wdsc) {
    int lin = blockIdx.x*256 + threadIdx.x;       // 9*64*64
    if (lin >= KK*64*64) return;
    int ci = lin & 63, co = (lin >> 6) & 63, k = lin >> 12;
    float v = wdsc[((size_t)(co*64 + ci))*KK + k];
    __nv_bfloat16 hi = __float2bfloat16(v);
    __nv_bfloat16 lo = __float2bfloat16(v - __bfloat162float(hi));
    uint32_t off = (uint32_t)(co*128 + ci*2);
    uint32_t sw = off ^ ((off >> 3) & 0x70);
    *(__nv_bfloat16*)((char*)g_wbf + (size_t)k*8192 + sw) = hi;
    *(__nv_bfloat16*)((char*)g_wbf + (size_t)(KK + k)*8192 + sw) = lo;
}

// ---------------- kernel 4: fused coords + sampling + mma.sync GEMM ----------------
// CTA: 128 pixels (N) x 64 co (M), K = 9 taps x 64 ci. 256 threads, 3 CTAs/SM.
__global__ void __launch_bounds__(256, 3)
main_kernel(const float* __restrict__ x,
            const float* __restrict__ gno_w, const float* __restrict__ gno_b,
            const float* __restrict__ b_dsc,
            float* __restrict__ out) {
    extern __shared__ __align__(16) char smem[];
    uint32_t sb = smem_u32(smem);
    float* iy_sh = (float*)(smem + OFF_IY);
    float* sums  = (float*)(smem + OFF_SUMS);

    int t = threadIdx.x, lane = t & 31, wid = t >> 5;
    int b = blockIdx.z, h = blockIdx.y, w0 = blockIdx.x * 128;
    if (t < 32) sums[t] = 0.f;

    // Phase 0: GN+tanh, outward cumsum, clamped iy for 128 pixels x 9 taps
    if (t < 128) {
        int p = t, wg = w0 + p;
        float v[9];
#pragma unroll
        for (int c = 0; c < 9; c++) {
            float raw = g_off[((size_t)(b*OC1 + c)*HH + h)*WW + wg];
            int g = c >> 1;
            float mean = g_offstats[(b*5+g)*2];
            float rstd = g_offstats[(b*5+g)*2+1];
            v[c] = tanhf((raw - mean)*rstd*gno_w[c] + gno_b[c]);
        }
        float cum[9];
        cum[4] = 0.f;
        cum[3] = v[3]; cum[2] = cum[3]+v[2]; cum[1] = cum[2]+v[1]; cum[0] = cum[1]+v[0];
        cum[5] = v[5]; cum[6] = cum[5]+v[6]; cum[7] = cum[6]+v[7]; cum[8] = cum[7]+v[8];
#pragma unroll
        for (int k = 0; k < 9; k++)
            iy_sh[k*128 + p] = fminf(fmaxf((float)h + cum[k], 0.f), 255.f);
    }

    const float* xb = x + (size_t)b*CIN*HW;
    int pixw = (wid & 3)*32 + lane;      // sampling: pixel this thread owns
    int ci0base = (wid >> 2)*32;         // sampling: ci chunk base

    // mma warp tiling: wm in {0,1} -> 32 co, wn in {0..3} -> 32 pix
    int wm = wid & 1, wn = wid >> 1;
    float acc[2][4][4];
#pragma unroll
    for (int i = 0; i < 2; i++)
#pragma unroll
        for (int j = 0; j < 4; j++)
#pragma unroll
            for (int l = 0; l < 4; l++) acc[i][j][l] = 0.f;

    for (int k = 0; k < KK; k++) {
        __syncthreads();   // previous mma phase done reading S/W; iy_sh ready (k=0)

        // ---- async copy this tap's weight tiles (pre-swizzled, L2-hot) ----
        {
            const char* whsrc = (const char*)g_wbf + (size_t)k*8192 + t*32;
            const char* wlsrc = (const char*)g_wbf + (size_t)(KK + k)*8192 + t*32;
            cpasync16(sb + OFF_WHI + t*32,      whsrc);
            cpasync16(sb + OFF_WHI + t*32 + 16, whsrc + 16);
            cpasync16(sb + OFF_WLO + t*32,      wlsrc);
            cpasync16(sb + OFF_WLO + t*32 + 16, wlsrc + 16);
            asm volatile("cp.async.commit_group;" ::: "memory");
        }

        // ---- sampling: S[pix][ci] bf16 hi/lo, swizzled 128B rows ----
        float iy = iy_sh[k*128 + pixw];
        float y0f = floorf(iy);
        float wy = iy - y0f;
        int y0 = (int)y0f;
        int y1 = min(y0 + 1, 255);
        int ix = min(max(w0 + pixw + k - 4, 0), 255);
        const float* p0 = xb + y0*WW + ix;
        const float* p1 = xb + y1*WW + ix;

#pragma unroll
        for (int g = 0; g < 4; g++) {
            int ci0 = ci0base + g*8;
            float v[8];
#pragma unroll
            for (int j = 0; j < 8; j++) {
                size_t o = (size_t)(ci0 + j)*HW;
                float a = __ldg(p0 + o), c = __ldg(p1 + o);
                v[j] = fmaf(c - a, wy, a);
            }
            uint32_t hp[4], lp[4];
#pragma unroll
            for (int j = 0; j < 4; j++) {
                __nv_bfloat162 h2 = __floats2bfloat162_rn(v[2*j], v[2*j+1]);
                float2 hf = __bfloat1622float2(h2);
                __nv_bfloat162 l2 = __floats2bfloat162_rn(v[2*j] - hf.x, v[2*j+1] - hf.y);
                memcpy(&hp[j], &h2, 4);
                memcpy(&lp[j], &l2, 4);
            }
            uint32_t off = (uint32_t)(pixw*128 + ci0*2);
            uint32_t sw = off ^ ((off >> 3) & 0x70);
            *(uint4*)(smem + OFF_SHI + sw) = make_uint4(hp[0], hp[1], hp[2], hp[3]);
            *(uint4*)(smem + OFF_SLO + sw) = make_uint4(lp[0], lp[1], lp[2], lp[3]);
        }

        asm volatile("cp.async.wait_group 0;" ::: "memory");
        __syncthreads();

        // ---- mma phase: 4 ksteps of 16 ci ----
#pragma unroll
        for (int kt = 0; kt < 4; kt++) {
            uint32_t ahi[2][4], alo[2][4];
#pragma unroll
            for (int mt = 0; mt < 2; mt++) {
                uint32_t row = (uint32_t)(wm*32 + mt*16 + (lane & 15));
                uint32_t c16 = (uint32_t)(kt*2 + (lane >> 4));
                uint32_t off = row*128 + c16*16;
                uint32_t sw = off ^ ((off >> 3) & 0x70);
                ldsm_x4(ahi[mt], sb + OFF_WHI + sw);
                ldsm_x4(alo[mt], sb + OFF_WLO + sw);
            }
            uint32_t bhi[4][2], blo[4][2];
#pragma unroll
            for (int nt = 0; nt < 4; nt++) {
                uint32_t row = (uint32_t)(wn*32 + nt*8 + (lane & 7));
                uint32_t c16 = (uint32_t)(kt*2 + ((lane >> 3) & 1));
                uint32_t off = row*128 + c16*16;
                uint32_t sw = off ^ ((off >> 3) & 0x70);
                ldsm_x2(bhi[nt], sb + OFF_SHI + sw);
                ldsm_x2(blo[nt], sb + OFF_SLO + sw);
            }
#pragma unroll
            for (int mt = 0; mt < 2; mt++)
#pragma unroll
                for (int nt = 0; nt < 4; nt++) {
                    mma16816(acc[mt][nt], ahi[mt], bhi[nt]);
                    mma16816(acc[mt][nt], alo[mt], bhi[nt]);
                    mma16816(acc[mt][nt], ahi[mt], blo[nt]);
                }
        }
    }

    // ---- epilogue: bias, store, GN partial sums ----
    {
        int q = lane >> 2;                    // co row within tile
        int pp = (lane & 3) * 2;              // pixel pair
        float s_l[2][2] = {{0.f,0.f},{0.f,0.f}}, q_l[2][2] = {{0.f,0.f},{0.f,0.f}};
#pragma unroll
        for (int mt = 0; mt < 2; mt++) {
            int cog = wm*32 + mt*16 + q;
            float b0 = __ldg(b_dsc + cog);
            float b1 = __ldg(b_dsc + cog + 8);
#pragma unroll
            for (int nt = 0; nt < 4; nt++) {
                int pix = wn*32 + nt*8 + pp;
                float v0 = acc[mt][nt][0] + b0;
                float v1 = acc[mt][nt][1] + b0;
                float v2 = acc[mt][nt][2] + b1;
                float v3 = acc[mt][nt][3] + b1;
                *(float2*)&out[((size_t)(b*64 + cog)*HH + h)*WW + w0 + pix]     = make_float2(v0, v1);
                *(float2*)&out[((size_t)(b*64 + cog + 8)*HH + h)*WW + w0 + pix] = make_float2(v2, v3);
                s_l[mt][0] += v0 + v1; q_l[mt][0] += v0*v0 + v1*v1;
                s_l[mt][1] += v2 + v3; q_l[mt][1] += v2*v2 + v3*v3;
            }
        }
#pragma unroll
        for (int mt = 0; mt < 2; mt++)
#pragma unroll
            for (int hf = 0; hf < 2; hf++) {
#pragma unroll
                for (int m = 1; m <= 2; m <<= 1) {
                    s_l[mt][hf] += __shfl_xor_sync(0xffffffff, s_l[mt][hf], m);
                    q_l[mt][hf] += __shfl_xor_sync(0xffffffff, q_l[mt][hf], m);
                }
                if ((lane & 3) == 0) {
                    int grp = (wm*32 + mt*16 + hf*8 + q) >> 2;
                    atomicAdd(&sums[2*grp],   s_l[mt][hf]);
                    atomicAdd(&sums[2*grp+1], q_l[mt][hf]);
                }
            }
    }
    __syncthreads();
    if (t < 32) {
        int bw = blockIdx.x + 2*h;     // 0..511 within batch
        g_part[((size_t)(b*512 + bw)*16 + (t >> 1))*2 + (t & 1)] = sums[t];
    }
}

// ---------------- kernel 5: reduce out-GN partials ----------------
__global__ void outstats_kernel() {
    int b = blockIdx.x >> 4, g = blockIdx.x & 15;
    int t = threadIdx.x;
    float s = 0.f, q = 0.f;
    for (int i = t; i < 512; i += 256) {
        size_t idx = ((size_t)(b*512 + i)*16 + g)*2;
        s += g_part[idx];
        q += g_part[idx + 1];
    }
    __shared__ float rs[256], rq[256];
    rs[t] = s; rq[t] = q; __syncthreads();
    for (int o = 128; o > 0; o >>= 1) {
        if (t < o) { rs[t] += rs[t+o]; rq[t] += rq[t+o]; }
        __syncthreads();
    }
    if (t == 0) {
        float n = 4.f * HW;
        float mean = rs[0] / n;
        float var = rq[0] / n - mean*mean;
        g_outmr[(b*16+g)*2]   = mean;
        g_outmr[(b*16+g)*2+1] = rsqrtf(var + 1e-5f);
    }
}

// ---------------- kernel 6: apply GN + ReLU ----------------
__global__ void apply_kernel(float* __restrict__ out,
                             const float* __restrict__ gn_w,
                             const float* __restrict__ gn_b) {
    int idx4 = blockIdx.x*blockDim.x + threadIdx.x;
    size_t base = (size_t)idx4 * 4;
    int co = (int)((base >> 16) & 63);
    int b  = (int)(base >> 22);
    int g  = co >> 2;
    float mean = g_outmr[(b*16+g)*2];
    float rstd = g_outmr[(b*16+g)*2+1];
    float sc = rstd * gn_w[co];
    float sh = gn_b[co] - mean * sc;
    float4 v = *(float4*)&out[base];
    v.x = fmaxf(fmaf(v.x, sc, sh), 0.f);
    v.y = fmaxf(fmaf(v.y, sc, sh), 0.f);
    v.z = fmaxf(fmaf(v.z, sc, sh), 0.f);
    v.w = fmaxf(fmaf(v.w, sc, sh), 0.f);
    *(float4*)&out[base] = v;
}

// ---------------- launch ----------------
extern "C" void kernel_launch(void* const* d_in, const int* in_sizes, int n_in,
                              void* d_out, int out_size) {
    const float* x     = (const float*)d_in[0];
    const float* w_off = (const float*)d_in[1];
    const float* b_off = (const float*)d_in[2];
    const float* gno_w = (const float*)d_in[3];
    const float* gno_b = (const float*)d_in[4];
    const float* w_dsc = (const float*)d_in[5];
    const float* b_dsc = (const float*)d_in[6];
    const float* gn_w  = (const float*)d_in[7];
    const float* gn_b  = (const float*)d_in[8];
    float* out = (float*)d_out;

    cudaFuncSetAttribute(main_kernel, cudaFuncAttributeMaxDynamicSharedMemorySize, SMEM_BYTES);

    conv1_kernel<<<dim3(WW/32, HH/8, BN), 256>>>(x, w_off, b_off);
    offstats_kernel<<<BN*5, 256>>>();
    wprep_kernel<<<(KK*64*64 + 255)/256, 256>>>(w_dsc);
    main_kernel<<<dim3(2, HH, BN), 256, SMEM_BYTES>>>(x, gno_w, gno_b, b_dsc, out);
    outstats_kernel<<<BN*16, 256>>>();
    apply_kernel<<<4096, 512>>>(out, gn_w, gn_b);
}

// round 10
// speedup vs baseline: 2.2877x; 1.1439x over previous
#include <cuda_runtime.h>
#include <cuda_bf16.h>
#include <cuda_fp16.h>
#include <cstdint>
#include <cstring>

#define BN 2
#define CIN 64
#define HH 256
#define WW 256
#define KK 9
#define OC1 10
#define HW (HH*WW)

// ---------------- scratch ----------------
__device__ float g_off[BN*OC1*HW];
__device__ float g_offpart[BN*256*20];    // per-conv1-block (sum,sumsq) x 10 ch
__device__ float g_offstats[BN*5*2];
__device__ __align__(16) __half g_wh[KK*4096];   // [k][swizzled 64co x 64ci] fp16
__device__ float g_part[BN*512*16*2];
__device__ float g_outmr[BN*16*2];

// ---------------- mma helpers (baseline PTX, no 'a' features) ----------------
__device__ __forceinline__ uint32_t smem_u32(const void* p) {
    uint32_t a;
    asm("{ .reg .u64 t; cvta.to.shared.u64 t, %1; cvt.u32.u64 %0, t; }" : "=r"(a) : "l"(p));
    return a;
}
__device__ __forceinline__ void ldsm_x4(uint32_t* r, uint32_t addr) {
    asm volatile("ldmatrix.sync.aligned.m8n8.x4.shared.b16 {%0,%1,%2,%3}, [%4];"
                 : "=r"(r[0]), "=r"(r[1]), "=r"(r[2]), "=r"(r[3]) : "r"(addr));
}
__device__ __forceinline__ void ldsm_x2(uint32_t* r, uint32_t addr) {
    asm volatile("ldmatrix.sync.aligned.m8n8.x2.shared.b16 {%0,%1}, [%2];"
                 : "=r"(r[0]), "=r"(r[1]) : "r"(addr));
}
__device__ __forceinline__ void mma16816h(float* d, const uint32_t* a, const uint32_t* b) {
    asm volatile("mma.sync.aligned.m16n8k16.row.col.f32.f16.f16.f32 "
                 "{%0,%1,%2,%3}, {%4,%5,%6,%7}, {%8,%9}, {%0,%1,%2,%3};"
                 : "+f"(d[0]), "+f"(d[1]), "+f"(d[2]), "+f"(d[3])
                 : "r"(a[0]), "r"(a[1]), "r"(a[2]), "r"(a[3]), "r"(b[0]), "r"(b[1]));
}
__device__ __forceinline__ void cpasync16(uint32_t saddr, const void* gptr) {
    asm volatile("cp.async.ca.shared.global [%0], [%1], 16;" :: "r"(saddr), "l"(gptr) : "memory");
}

// smem layout (dynamic), single stage, fp16 single-pass
#define OFF_SH   0           // [128 pix][64 ci] fp16, 128B rows, swizzled (16 KB)
#define OFF_WH   16384       // [64 co][64 ci] fp16, 128B rows, swizzled (8 KB)
#define OFF_IY   24576       // 9*128 floats (4608 B)
#define OFF_SUMS 29184       // 32 floats
#define SMEM_BYTES 29312

// ---------------- kernel 1: 3x3 conv, 64 -> 10 channels (+ GN stat partials) ----------------
// 2 input channels per barrier pair.
__global__ void conv1_kernel(const float* __restrict__ x,
                             const float* __restrict__ w,
                             const float* __restrict__ bias) {
    int b = blockIdx.z, w0 = blockIdx.x * 32, h0 = blockIdx.y * 8;
    int t = threadIdx.x;
    int tw = t & 31, th = t >> 5;
    __shared__ float xs[2][10][34];
    __shared__ float ws[2][OC1][9];
    __shared__ float red[8][20];
    float acc[OC1];
#pragma unroll
    for (int o = 0; o < OC1; o++) acc[o] = 0.f;

    for (int ci = 0; ci < CIN; ci += 2) {
        for (int i = t; i < 680; i += 256) {
            int half = i >= 340;
            int li = half ? i - 340 : i;
            int r = li / 34, c = li % 34;
            int hy = h0 - 1 + r, wx = w0 - 1 + c;
            float v = 0.f;
            if (hy >= 0 && hy < HH && wx >= 0 && wx < WW)
                v = __ldg(&x[((size_t)(b*CIN + ci + half)*HH + hy)*WW + wx]);
            xs[half][r][c] = v;
        }
        if (t < OC1*9*2) {
            int half = t >= OC1*9;
            int li = half ? t - OC1*9 : t;
            ws[half][li/9][li%9] = __ldg(&w[(li/9)*CIN*9 + (ci + half)*9 + (li%9)]);
        }
        __syncthreads();

#pragma unroll
        for (int half = 0; half < 2; half++) {
            float xv[9];
#pragma unroll
            for (int dy = 0; dy < 3; dy++)
#pragma unroll
                for (int dx = 0; dx < 3; dx++)
                    xv[dy*3+dx] = xs[half][th+dy][tw+dx];
#pragma unroll
            for (int o = 0; o < OC1; o++) {
                float a = acc[o];
#pragma unroll
                for (int tp = 0; tp < 9; tp++) a = fmaf(ws[half][o][tp], xv[tp], a);
                acc[o] = a;
            }
        }
        __syncthreads();
    }
    int lane = t & 31, wid = t >> 5;
#pragma unroll
    for (int o = 0; o < OC1; o++) {
        float v = acc[o] + bias[o];
        g_off[((size_t)(b*OC1 + o)*HH + h0 + th)*WW + w0 + tw] = v;
        float s = v, q = v*v;
#pragma unroll
        for (int m = 16; m; m >>= 1) {
            s += __shfl_xor_sync(0xffffffff, s, m);
            q += __shfl_xor_sync(0xffffffff, q, m);
        }
        if (lane == 0) { red[wid][o*2] = s; red[wid][o*2+1] = q; }
    }
    __syncthreads();
    if (t < 20) {
        float a = 0.f;
#pragma unroll
        for (int wq = 0; wq < 8; wq++) a += red[wq][t];
        int blk = blockIdx.x + 8*blockIdx.y;   // 0..255
        g_offpart[((size_t)(b*256) + blk)*20 + t] = a;
    }
}

// ---------------- kernel 2: reduce offset GN partials ----------------
__global__ void offstats_kernel() {
    int b = blockIdx.x / 5, g = blockIdx.x % 5;
    int t = threadIdx.x;
    float s = 0.f, q = 0.f;
    for (int i = t; i < 256; i += 256) {
        const float* p = g_offpart + ((size_t)(b*256) + i)*20;
        s += p[(2*g)*2]   + p[(2*g+1)*2];
        q += p[(2*g)*2+1] + p[(2*g+1)*2+1];
    }
    __shared__ float rs[256], rq[256];
    rs[t] = s; rq[t] = q; __syncthreads();
    for (int o = 128; o > 0; o >>= 1) {
        if (t < o) { rs[t] += rs[t+o]; rq[t] += rq[t+o]; }
        __syncthreads();
    }
    if (t == 0) {
        float n = (float)(2*HW);
        float mean = rs[0] / n;
        float var = rq[0] / n - mean*mean;
        g_offstats[(b*5+g)*2]   = mean;
        g_offstats[(b*5+g)*2+1] = rsqrtf(var + 1e-5f);
    }
}

// ---------------- kernel 3: w_dsc -> fp16, [k][co][ci] swizzled ----------------
__global__ void wprep_kernel(const float* __restrict__ wdsc) {
    int lin = blockIdx.x*256 + threadIdx.x;       // 9*64*64
    if (lin >= KK*64*64) return;
    int ci = lin & 63, co = (lin >> 6) & 63, k = lin >> 12;
    float v = wdsc[((size_t)(co*64 + ci))*KK + k];
    uint32_t off = (uint32_t)(co*128 + ci*2);
    uint32_t sw = off ^ ((off >> 3) & 0x70);
    *(__half*)((char*)g_wh + (size_t)k*8192 + sw) = __float2half(v);
}

// ---------------- kernel 4: fused coords + sampling + fp16 mma.sync GEMM ----------------
// CTA: 128 pixels (N) x 64 co (M), K = 9 taps x 64 ci. 256 threads, 3 CTAs/SM.
__global__ void __launch_bounds__(256, 3)
main_kernel(const float* __restrict__ x,
            const float* __restrict__ gno_w, const float* __restrict__ gno_b,
            const float* __restrict__ b_dsc,
            float* __restrict__ out) {
    extern __shared__ __align__(16) char smem[];
    uint32_t sb = smem_u32(smem);
    float* iy_sh = (float*)(smem + OFF_IY);
    float* sums  = (float*)(smem + OFF_SUMS);

    int t = threadIdx.x, lane = t & 31, wid = t >> 5;
    int b = blockIdx.z, h = blockIdx.y, w0 = blockIdx.x * 128;
    if (t < 32) sums[t] = 0.f;

    // Phase 0: GN+tanh, outward cumsum, clamped iy for 128 pixels x 9 taps
    if (t < 128) {
        int p = t, wg = w0 + p;
        float v[9];
#pragma unroll
        for (int c = 0; c < 9; c++) {
            float raw = g_off[((size_t)(b*OC1 + c)*HH + h)*WW + wg];
            int g = c >> 1;
            float mean = g_offstats[(b*5+g)*2];
            float rstd = g_offstats[(b*5+g)*2+1];
            v[c] = tanhf((raw - mean)*rstd*gno_w[c] + gno_b[c]);
        }
        float cum[9];
        cum[4] = 0.f;
        cum[3] = v[3]; cum[2] = cum[3]+v[2]; cum[1] = cum[2]+v[1]; cum[0] = cum[1]+v[0];
        cum[5] = v[5]; cum[6] = cum[5]+v[6]; cum[7] = cum[6]+v[7]; cum[8] = cum[7]+v[8];
#pragma unroll
        for (int k = 0; k < 9; k++)
            iy_sh[k*128 + p] = fminf(fmaxf((float)h + cum[k], 0.f), 255.f);
    }

    const float* xb = x + (size_t)b*CIN*HW;
    int pixw = (wid & 3)*32 + lane;      // sampling: pixel this thread owns
    int ci0base = (wid >> 2)*32;         // sampling: ci chunk base

    // mma warp tiling: wm in {0,1} -> 32 co, wn in {0..3} -> 32 pix
    int wm = wid & 1, wn = wid >> 1;
    float acc[2][4][4];
#pragma unroll
    for (int i = 0; i < 2; i++)
#pragma unroll
        for (int j = 0; j < 4; j++)
#pragma unroll
            for (int l = 0; l < 4; l++) acc[i][j][l] = 0.f;

    for (int k = 0; k < KK; k++) {
        __syncthreads();   // previous mma phase done reading S/W; iy_sh ready (k=0)

        // ---- async copy this tap's fp16 weight tile (pre-swizzled, L2-hot) ----
        {
            const char* wsrc = (const char*)g_wh + (size_t)k*8192 + t*32;
            cpasync16(sb + OFF_WH + t*32,      wsrc);
            cpasync16(sb + OFF_WH + t*32 + 16, wsrc + 16);
            asm volatile("cp.async.commit_group;" ::: "memory");
        }

        // ---- sampling: S[pix][ci] fp16, swizzled 128B rows ----
        float iy = iy_sh[k*128 + pixw];
        float y0f = floorf(iy);
        float wy = iy - y0f;
        int y0 = (int)y0f;
        int y1 = min(y0 + 1, 255);
        int ix = min(max(w0 + pixw + k - 4, 0), 255);
        const float* p0 = xb + y0*WW + ix;
        const float* p1 = xb + y1*WW + ix;

#pragma unroll
        for (int g = 0; g < 4; g++) {
            int ci0 = ci0base + g*8;
            float v[8];
#pragma unroll
            for (int j = 0; j < 8; j++) {
                size_t o = (size_t)(ci0 + j)*HW;
                float a = __ldg(p0 + o), c = __ldg(p1 + o);
                v[j] = fmaf(c - a, wy, a);
            }
            uint32_t hp[4];
#pragma unroll
            for (int j = 0; j < 4; j++) {
                __half2 h2 = __floats2half2_rn(v[2*j], v[2*j+1]);
                memcpy(&hp[j], &h2, 4);
            }
            uint32_t off = (uint32_t)(pixw*128 + ci0*2);
            uint32_t sw = off ^ ((off >> 3) & 0x70);
            *(uint4*)(smem + OFF_SH + sw) = make_uint4(hp[0], hp[1], hp[2], hp[3]);
        }

        asm volatile("cp.async.wait_group 0;" ::: "memory");
        __syncthreads();

        // ---- mma phase: 4 ksteps of 16 ci, single fp16 pass ----
#pragma unroll
        for (int kt = 0; kt < 4; kt++) {
            uint32_t af[2][4];
#pragma unroll
            for (int mt = 0; mt < 2; mt++) {
                uint32_t row = (uint32_t)(wm*32 + mt*16 + (lane & 15));
                uint32_t c16 = (uint32_t)(kt*2 + (lane >> 4));
                uint32_t off = row*128 + c16*16;
                uint32_t sw = off ^ ((off >> 3) & 0x70);
                ldsm_x4(af[mt], sb + OFF_WH + sw);
            }
            uint32_t bf[4][2];
#pragma unroll
            for (int nt = 0; nt < 4; nt++) {
                uint32_t row = (uint32_t)(wn*32 + nt*8 + (lane & 7));
                uint32_t c16 = (uint32_t)(kt*2 + ((lane >> 3) & 1));
                uint32_t off = row*128 + c16*16;
                uint32_t sw = off ^ ((off >> 3) & 0x70);
                ldsm_x2(bf[nt], sb + OFF_SH + sw);
            }
#pragma unroll
            for (int mt = 0; mt < 2; mt++)
#pragma unroll
                for (int nt = 0; nt < 4; nt++)
                    mma16816h(acc[mt][nt], af[mt], bf[nt]);
        }
    }

    // ---- epilogue: bias, store, GN partial sums ----
    {
        int q = lane >> 2;                    // co row within tile
        int pp = (lane & 3) * 2;              // pixel pair
        float s_l[2][2] = {{0.f,0.f},{0.f,0.f}}, q_l[2][2] = {{0.f,0.f},{0.f,0.f}};
#pragma unroll
        for (int mt = 0; mt < 2; mt++) {
            int cog = wm*32 + mt*16 + q;
            float b0 = __ldg(b_dsc + cog);
            float b1 = __ldg(b_dsc + cog + 8);
#pragma unroll
            for (int nt = 0; nt < 4; nt++) {
                int pix = wn*32 + nt*8 + pp;
                float v0 = acc[mt][nt][0] + b0;
                float v1 = acc[mt][nt][1] + b0;
                float v2 = acc[mt][nt][2] + b1;
                float v3 = acc[mt][nt][3] + b1;
                *(float2*)&out[((size_t)(b*64 + cog)*HH + h)*WW + w0 + pix]     = make_float2(v0, v1);
                *(float2*)&out[((size_t)(b*64 + cog + 8)*HH + h)*WW + w0 + pix] = make_float2(v2, v3);
                s_l[mt][0] += v0 + v1; q_l[mt][0] += v0*v0 + v1*v1;
                s_l[mt][1] += v2 + v3; q_l[mt][1] += v2*v2 + v3*v3;
            }
        }
#pragma unroll
        for (int mt = 0; mt < 2; mt++)
#pragma unroll
            for (int hf = 0; hf < 2; hf++) {
#pragma unroll
                for (int m = 1; m <= 2; m <<= 1) {
                    s_l[mt][hf] += __shfl_xor_sync(0xffffffff, s_l[mt][hf], m);
                    q_l[mt][hf] += __shfl_xor_sync(0xffffffff, q_l[mt][hf], m);
                }
                if ((lane & 3) == 0) {
                    int grp = (wm*32 + mt*16 + hf*8 + q) >> 2;
                    atomicAdd(&sums[2*grp],   s_l[mt][hf]);
                    atomicAdd(&sums[2*grp+1], q_l[mt][hf]);
                }
            }
    }
    __syncthreads();
    if (t < 32) {
        int bw = blockIdx.x + 2*h;     // 0..511 within batch
        g_part[((size_t)(b*512 + bw)*16 + (t >> 1))*2 + (t & 1)] = sums[t];
    }
}

// ---------------- kernel 5: reduce out-GN partials ----------------
__global__ void outstats_kernel() {
    int b = blockIdx.x >> 4, g = blockIdx.x & 15;
    int t = threadIdx.x;
    float s = 0.f, q = 0.f;
    for (int i = t; i < 512; i += 256) {
        size_t idx = ((size_t)(b*512 + i)*16 + g)*2;
        s += g_part[idx];
        q += g_part[idx + 1];
    }
    __shared__ float rs[256], rq[256];
    rs[t] = s; rq[t] = q; __syncthreads();
    for (int o = 128; o > 0; o >>= 1) {
        if (t < o) { rs[t] += rs[t+o]; rq[t] += rq[t+o]; }
        __syncthreads();
    }
    if (t == 0) {
        float n = 4.f * HW;
        float mean = rs[0] / n;
        float var = rq[0] / n - mean*mean;
        g_outmr[(b*16+g)*2]   = mean;
        g_outmr[(b*16+g)*2+1] = rsqrtf(var + 1e-5f);
    }
}

// ---------------- kernel 6: apply GN + ReLU ----------------
__global__ void apply_kernel(float* __restrict__ out,
                             const float* __restrict__ gn_w,
                             const float* __restrict__ gn_b) {
    int idx4 = blockIdx.x*blockDim.x + threadIdx.x;
    size_t base = (size_t)idx4 * 4;
    int co = (int)((base >> 16) & 63);
    int b  = (int)(base >> 22);
    int g  = co >> 2;
    float mean = g_outmr[(b*16+g)*2];
    float rstd = g_outmr[(b*16+g)*2+1];
    float sc = rstd * gn_w[co];
    float sh = gn_b[co] - mean * sc;
    float4 v = *(float4*)&out[base];
    v.x = fmaxf(fmaf(v.x, sc, sh), 0.f);
    v.y = fmaxf(fmaf(v.y, sc, sh), 0.f);
    v.z = fmaxf(fmaf(v.z, sc, sh), 0.f);
    v.w = fmaxf(fmaf(v.w, sc, sh), 0.f);
    *(float4*)&out[base] = v;
}

// ---------------- launch ----------------
extern "C" void kernel_launch(void* const* d_in, const int* in_sizes, int n_in,
                              void* d_out, int out_size) {
    const float* x     = (const float*)d_in[0];
    const float* w_off = (const float*)d_in[1];
    const float* b_off = (const float*)d_in[2];
    const float* gno_w = (const float*)d_in[3];
    const float* gno_b = (const float*)d_in[4];
    const float* w_dsc = (const float*)d_in[5];
    const float* b_dsc = (const float*)d_in[6];
    const float* gn_w  = (const float*)d_in[7];
    const float* gn_b  = (const float*)d_in[8];
    float* out = (float*)d_out;

    cudaFuncSetAttribute(main_kernel, cudaFuncAttributeMaxDynamicSharedMemorySize, SMEM_BYTES);

    conv1_kernel<<<dim3(WW/32, HH/8, BN), 256>>>(x, w_off, b_off);
    offstats_kernel<<<BN*5, 256>>>();
    wprep_kernel<<<(KK*64*64 + 255)/256, 256>>>(w_dsc);
    main_kernel<<<dim3(2, HH, BN), 256, SMEM_BYTES>>>(x, gno_w, gno_b, b_dsc, out);
    outstats_kernel<<<BN*16, 256>>>();
    apply_kernel<<<4096, 512>>>(out, gn_w, gn_b);
}

// round 11
// speedup vs baseline: 2.4699x; 1.0796x over previous
#include <cuda_runtime.h>
#include <cuda_bf16.h>
#include <cuda_fp16.h>
#include <cstdint>
#include <cstring>

#define BN 2
#define CIN 64
#define HH 256
#define WW 256
#define KK 9
#define OC1 10
#define HW (HH*WW)

// ---------------- scratch ----------------
__device__ float g_off[BN*OC1*HW];
__device__ float g_offpart[BN*128*20];    // per-conv1-block (sum,sumsq) x 10 ch
__device__ float g_offstats[BN*5*2];
__device__ __align__(16) __half g_wh[KK*4096];   // [k][swizzled 64co x 64ci] fp16
__device__ float g_part[BN*512*16*2];
__device__ float g_outmr[BN*16*2];

// ---------------- mma helpers (baseline PTX, no 'a' features) ----------------
__device__ __forceinline__ uint32_t smem_u32(const void* p) {
    uint32_t a;
    asm("{ .reg .u64 t; cvta.to.shared.u64 t, %1; cvt.u32.u64 %0, t; }" : "=r"(a) : "l"(p));
    return a;
}
__device__ __forceinline__ void ldsm_x4(uint32_t* r, uint32_t addr) {
    asm volatile("ldmatrix.sync.aligned.m8n8.x4.shared.b16 {%0,%1,%2,%3}, [%4];"
                 : "=r"(r[0]), "=r"(r[1]), "=r"(r[2]), "=r"(r[3]) : "r"(addr));
}
__device__ __forceinline__ void ldsm_x2(uint32_t* r, uint32_t addr) {
    asm volatile("ldmatrix.sync.aligned.m8n8.x2.shared.b16 {%0,%1}, [%2];"
                 : "=r"(r[0]), "=r"(r[1]) : "r"(addr));
}
__device__ __forceinline__ void mma16816h(float* d, const uint32_t* a, const uint32_t* b) {
    asm volatile("mma.sync.aligned.m16n8k16.row.col.f32.f16.f16.f32 "
                 "{%0,%1,%2,%3}, {%4,%5,%6,%7}, {%8,%9}, {%0,%1,%2,%3};"
                 : "+f"(d[0]), "+f"(d[1]), "+f"(d[2]), "+f"(d[3])
                 : "r"(a[0]), "r"(a[1]), "r"(a[2]), "r"(a[3]), "r"(b[0]), "r"(b[1]));
}
__device__ __forceinline__ void cpasync16(uint32_t saddr, const void* gptr) {
    asm volatile("cp.async.ca.shared.global [%0], [%1], 16;" :: "r"(saddr), "l"(gptr) : "memory");
}

// smem layout (dynamic), 2 stages
#define OFF_SH(st)  ((st)*16384)            // [128 pix][64 ci] fp16 swizzled
#define OFF_WH(st)  (32768 + (st)*8192)     // [64 co][64 ci] fp16 swizzled
#define OFF_IY   49152                       // 9*128 floats
#define OFF_SUMS 53760                       // 32 floats
#define SMEM_BYTES 53888

// ---------------- kernel 1: 3x3 conv, 64 -> 10 channels (+ GN stat partials) ----------------
// 64x8 tile, 2 px/thread, 2 ci per stage.
__global__ void conv1_kernel(const float* __restrict__ x,
                             const float* __restrict__ w,
                             const float* __restrict__ bias) {
    int b = blockIdx.z, w0 = blockIdx.x * 64, h0 = blockIdx.y * 8;
    int t = threadIdx.x;
    int tw = t & 31, th = t >> 5;
    __shared__ float xs[2][10][66];
    __shared__ float ws[2][OC1][9];
    __shared__ float red[8][20];
    float acc[2][OC1];
#pragma unroll
    for (int p = 0; p < 2; p++)
#pragma unroll
        for (int o = 0; o < OC1; o++) acc[p][o] = 0.f;

    for (int ci = 0; ci < CIN; ci += 2) {
        for (int i = t; i < 1320; i += 256) {
            int half = i >= 660;
            int li = half ? i - 660 : i;
            int r = li / 66, c = li % 66;
            int hy = h0 - 1 + r, wx = w0 - 1 + c;
            float v = 0.f;
            if (hy >= 0 && hy < HH && wx >= 0 && wx < WW)
                v = __ldg(&x[((size_t)(b*CIN + ci + half)*HH + hy)*WW + wx]);
            xs[half][r][c] = v;
        }
        if (t < OC1*9*2) {
            int half = t >= OC1*9;
            int li = half ? t - OC1*9 : t;
            ws[half][li/9][li%9] = __ldg(&w[(li/9)*CIN*9 + (ci + half)*9 + (li%9)]);
        }
        __syncthreads();

#pragma unroll
        for (int half = 0; half < 2; half++) {
#pragma unroll
            for (int p = 0; p < 2; p++) {
                float xv[9];
#pragma unroll
                for (int dy = 0; dy < 3; dy++)
#pragma unroll
                    for (int dx = 0; dx < 3; dx++)
                        xv[dy*3+dx] = xs[half][th+dy][tw + p*32 + dx];
#pragma unroll
                for (int o = 0; o < OC1; o++) {
                    float a = acc[p][o];
#pragma unroll
                    for (int tp = 0; tp < 9; tp++) a = fmaf(ws[half][o][tp], xv[tp], a);
                    acc[p][o] = a;
                }
            }
        }
        __syncthreads();
    }
    int lane = t & 31, wid = t >> 5;
#pragma unroll
    for (int o = 0; o < OC1; o++) {
        float v0 = acc[0][o] + bias[o];
        float v1 = acc[1][o] + bias[o];
        g_off[((size_t)(b*OC1 + o)*HH + h0 + th)*WW + w0 + tw]      = v0;
        g_off[((size_t)(b*OC1 + o)*HH + h0 + th)*WW + w0 + tw + 32] = v1;
        float s = v0 + v1, q = v0*v0 + v1*v1;
#pragma unroll
        for (int m = 16; m; m >>= 1) {
            s += __shfl_xor_sync(0xffffffff, s, m);
            q += __shfl_xor_sync(0xffffffff, q, m);
        }
        if (lane == 0) { red[wid][o*2] = s; red[wid][o*2+1] = q; }
    }
    __syncthreads();
    if (t < 20) {
        float a = 0.f;
#pragma unroll
        for (int wq = 0; wq < 8; wq++) a += red[wq][t];
        int blk = blockIdx.x + 4*blockIdx.y;   // 0..127
        g_offpart[((size_t)(b*128) + blk)*20 + t] = a;
    }
}

// ---------------- kernel 2: reduce offset GN partials ----------------
__global__ void offstats_kernel() {
    int b = blockIdx.x / 5, g = blockIdx.x % 5;
    int t = threadIdx.x;
    float s = 0.f, q = 0.f;
    if (t < 128) {
        const float* p = g_offpart + ((size_t)(b*128) + t)*20;
        s = p[(2*g)*2]   + p[(2*g+1)*2];
        q = p[(2*g)*2+1] + p[(2*g+1)*2+1];
    }
    __shared__ float rs[256], rq[256];
    rs[t] = s; rq[t] = q; __syncthreads();
    for (int o = 128; o > 0; o >>= 1) {
        if (t < o) { rs[t] += rs[t+o]; rq[t] += rq[t+o]; }
        __syncthreads();
    }
    if (t == 0) {
        float n = (float)(2*HW);
        float mean = rs[0] / n;
        float var = rq[0] / n - mean*mean;
        g_offstats[(b*5+g)*2]   = mean;
        g_offstats[(b*5+g)*2+1] = rsqrtf(var + 1e-5f);
    }
}

// ---------------- kernel 3: w_dsc -> fp16, [k][co][ci] swizzled ----------------
__global__ void wprep_kernel(const float* __restrict__ wdsc) {
    int lin = blockIdx.x*256 + threadIdx.x;       // 9*64*64
    if (lin >= KK*64*64) return;
    int ci = lin & 63, co = (lin >> 6) & 63, k = lin >> 12;
    float v = wdsc[((size_t)(co*64 + ci))*KK + k];
    uint32_t off = (uint32_t)(co*128 + ci*2);
    uint32_t sw = off ^ ((off >> 3) & 0x70);
    *(__half*)((char*)g_wh + (size_t)k*8192 + sw) = __float2half(v);
}

// ---------------- kernel 4: pipelined coords + sampling + fp16 mma.sync GEMM ----------------
// CTA: 128 pixels (N) x 64 co (M), K = 9 taps x 64 ci. 256 threads, 3 CTAs/SM.
// Single barrier per tap: sample tap k+1 interleaved with mma of tap k (double-buffered S/W).
__global__ void __launch_bounds__(256, 3)
main_kernel(const float* __restrict__ x,
            const float* __restrict__ gno_w, const float* __restrict__ gno_b,
            const float* __restrict__ b_dsc,
            float* __restrict__ out) {
    extern __shared__ __align__(16) char smem[];
    uint32_t sb = smem_u32(smem);
    float* iy_sh = (float*)(smem + OFF_IY);
    float* sums  = (float*)(smem + OFF_SUMS);

    int t = threadIdx.x, lane = t & 31, wid = t >> 5;
    int b = blockIdx.z, h = blockIdx.y, w0 = blockIdx.x * 128;
    if (t < 32) sums[t] = 0.f;

    // Phase 0: GN+tanh, outward cumsum, clamped iy for 128 pixels x 9 taps
    if (t < 128) {
        int p = t, wg = w0 + p;
        float v[9];
#pragma unroll
        for (int c = 0; c < 9; c++) {
            float raw = g_off[((size_t)(b*OC1 + c)*HH + h)*WW + wg];
            int g = c >> 1;
            float mean = g_offstats[(b*5+g)*2];
            float rstd = g_offstats[(b*5+g)*2+1];
            v[c] = tanhf((raw - mean)*rstd*gno_w[c] + gno_b[c]);
        }
        float cum[9];
        cum[4] = 0.f;
        cum[3] = v[3]; cum[2] = cum[3]+v[2]; cum[1] = cum[2]+v[1]; cum[0] = cum[1]+v[0];
        cum[5] = v[5]; cum[6] = cum[5]+v[6]; cum[7] = cum[6]+v[7]; cum[8] = cum[7]+v[8];
#pragma unroll
        for (int k = 0; k < 9; k++)
            iy_sh[k*128 + p] = fminf(fmaxf((float)h + cum[k], 0.f), 255.f);
    }

    const float* xb = x + (size_t)b*CIN*HW;
    int pixw = (wid & 3)*32 + lane;      // sampling: pixel this thread owns
    int ci0base = (wid >> 2)*32;         // sampling: ci chunk base
    int wm = wid & 1, wn = wid >> 1;     // mma warp tiling

    float acc[2][4][4];
#pragma unroll
    for (int i = 0; i < 2; i++)
#pragma unroll
        for (int j = 0; j < 4; j++)
#pragma unroll
            for (int l = 0; l < 4; l++) acc[i][j][l] = 0.f;

    // sampling helpers
    auto samp_setup = [&](int k, float& wy, const float*& p0, const float*& p1) {
        float iy = iy_sh[k*128 + pixw];
        float y0f = floorf(iy);
        wy = iy - y0f;
        int y0 = (int)y0f;
        int y1 = min(y0 + 1, 255);
        int ix = min(max(w0 + pixw + k - 4, 0), 255);
        p0 = xb + y0*WW + ix;
        p1 = xb + y1*WW + ix;
    };
    auto ldg8 = [&](const float* p0, const float* p1, float wy, int g, float* v) {
        int ci0 = ci0base + g*8;
#pragma unroll
        for (int j = 0; j < 8; j++) {
            size_t o = (size_t)(ci0 + j)*HW;
            float a = __ldg(p0 + o), c = __ldg(p1 + o);
            v[j] = fmaf(c - a, wy, a);
        }
    };
    auto sts8 = [&](int g, uint32_t bufoff, const float* v) {
        int ci0 = ci0base + g*8;
        uint32_t hp[4];
#pragma unroll
        for (int j = 0; j < 4; j++) {
            __half2 h2 = __floats2half2_rn(v[2*j], v[2*j+1]);
            memcpy(&hp[j], &h2, 4);
        }
        uint32_t off = (uint32_t)(pixw*128 + ci0*2);
        uint32_t sw = off ^ ((off >> 3) & 0x70);
        *(uint4*)(smem + bufoff + sw) = make_uint4(hp[0], hp[1], hp[2], hp[3]);
    };
    auto wcopy = [&](int k, uint32_t bufoff) {
        const char* wsrc = (const char*)g_wh + (size_t)k*8192 + t*32;
        cpasync16(sb + bufoff + t*32,      wsrc);
        cpasync16(sb + bufoff + t*32 + 16, wsrc + 16);
        asm volatile("cp.async.commit_group;" ::: "memory");
    };
    auto mma_kt = [&](int kt, uint32_t soff, uint32_t woff) {
        uint32_t af[2][4];
#pragma unroll
        for (int mt = 0; mt < 2; mt++) {
            uint32_t row = (uint32_t)(wm*32 + mt*16 + (lane & 15));
            uint32_t c16 = (uint32_t)(kt*2 + (lane >> 4));
            uint32_t off = row*128 + c16*16;
            uint32_t sw = off ^ ((off >> 3) & 0x70);
            ldsm_x4(af[mt], sb + woff + sw);
        }
        uint32_t bf[4][2];
#pragma unroll
        for (int nt = 0; nt < 4; nt++) {
            uint32_t row = (uint32_t)(wn*32 + nt*8 + (lane & 7));
            uint32_t c16 = (uint32_t)(kt*2 + ((lane >> 3) & 1));
            uint32_t off = row*128 + c16*16;
            uint32_t sw = off ^ ((off >> 3) & 0x70);
            ldsm_x2(bf[nt], sb + soff + sw);
        }
#pragma unroll
        for (int mt = 0; mt < 2; mt++)
#pragma unroll
            for (int nt = 0; nt < 4; nt++)
                mma16816h(acc[mt][nt], af[mt], bf[nt]);
    };

    // ---- prologue: W0 + sample tap 0 into stage 0 ----
    wcopy(0, OFF_WH(0));
    __syncthreads();           // iy_sh visible
    {
        float wy; const float *p0, *p1;
        samp_setup(0, wy, p0, p1);
#pragma unroll
        for (int g = 0; g < 4; g++) {
            float v[8];
            ldg8(p0, p1, wy, g, v);
            sts8(g, OFF_SH(0), v);
        }
    }
    asm volatile("cp.async.wait_group 0;" ::: "memory");
    __syncthreads();           // sbuf0 + wbuf0 ready

    // ---- main loop: mma tap k, sample tap k+1, one barrier per tap ----
#pragma unroll 1
    for (int k = 0; k < KK; k++) {
        int st = k & 1, ns = st ^ 1;
        bool pf = (k < KK-1);
        uint32_t soff = OFF_SH(st), woff = OFF_WH(st);

        float wy = 0.f; const float *p0 = xb, *p1 = xb;
        if (pf) {
            wcopy(k+1, OFF_WH(ns));
            samp_setup(k+1, wy, p0, p1);
        }

#pragma unroll
        for (int g = 0; g < 4; g++) {
            float v[8];
            if (pf) ldg8(p0, p1, wy, g, v);    // LDG latency hides under mma below
            mma_kt(g, soff, woff);
            if (pf) sts8(g, OFF_SH(ns), v);
        }

        if (pf) { asm volatile("cp.async.wait_group 0;" ::: "memory"); }
        __syncthreads();
    }

    // ---- epilogue: bias, store, GN partial sums ----
    {
        int q = lane >> 2;                    // co row within tile
        int pp = (lane & 3) * 2;              // pixel pair
        float s_l[2][2] = {{0.f,0.f},{0.f,0.f}}, q_l[2][2] = {{0.f,0.f},{0.f,0.f}};
#pragma unroll
        for (int mt = 0; mt < 2; mt++) {
            int cog = wm*32 + mt*16 + q;
            float b0 = __ldg(b_dsc + cog);
            float b1 = __ldg(b_dsc + cog + 8);
#pragma unroll
            for (int nt = 0; nt < 4; nt++) {
                int pix = wn*32 + nt*8 + pp;
                float v0 = acc[mt][nt][0] + b0;
                float v1 = acc[mt][nt][1] + b0;
                float v2 = acc[mt][nt][2] + b1;
                float v3 = acc[mt][nt][3] + b1;
                *(float2*)&out[((size_t)(b*64 + cog)*HH + h)*WW + w0 + pix]     = make_float2(v0, v1);
                *(float2*)&out[((size_t)(b*64 + cog + 8)*HH + h)*WW + w0 + pix] = make_float2(v2, v3);
                s_l[mt][0] += v0 + v1; q_l[mt][0] += v0*v0 + v1*v1;
                s_l[mt][1] += v2 + v3; q_l[mt][1] += v2*v2 + v3*v3;
            }
        }
#pragma unroll
        for (int mt = 0; mt < 2; mt++)
#pragma unroll
            for (int hf = 0; hf < 2; hf++) {
#pragma unroll
                for (int m = 1; m <= 2; m <<= 1) {
                    s_l[mt][hf] += __shfl_xor_sync(0xffffffff, s_l[mt][hf], m);
                    q_l[mt][hf] += __shfl_xor_sync(0xffffffff, q_l[mt][hf], m);
                }
                if ((lane & 3) == 0) {
                    int grp = (wm*32 + mt*16 + hf*8 + q) >> 2;
                    atomicAdd(&sums[2*grp],   s_l[mt][hf]);
                    atomicAdd(&sums[2*grp+1], q_l[mt][hf]);
                }
            }
    }
    __syncthreads();
    if (t < 32) {
        int bw = blockIdx.x + 2*h;     // 0..511 within batch
        g_part[((size_t)(b*512 + bw)*16 + (t >> 1))*2 + (t & 1)] = sums[t];
    }
}

// ---------------- kernel 5: reduce out-GN partials ----------------
__global__ void outstats_kernel() {
    int b = blockIdx.x >> 4, g = blockIdx.x & 15;
    int t = threadIdx.x;
    float s = 0.f, q = 0.f;
    for (int i = t; i < 512; i += 256) {
        size_t idx = ((size_t)(b*512 + i)*16 + g)*2;
        s += g_part[idx];
        q += g_part[idx + 1];
    }
    __shared__ float rs[256], rq[256];
    rs[t] = s; rq[t] = q; __syncthreads();
    for (int o = 128; o > 0; o >>= 1) {
        if (t < o) { rs[t] += rs[t+o]; rq[t] += rq[t+o]; }
        __syncthreads();
    }
    if (t == 0) {
        float n = 4.f * HW;
        float mean = rs[0] / n;
        float var = rq[0] / n - mean*mean;
        g_outmr[(b*16+g)*2]   = mean;
        g_outmr[(b*16+g)*2+1] = rsqrtf(var + 1e-5f);
    }
}

// ---------------- kernel 6: apply GN + ReLU ----------------
__global__ void apply_kernel(float* __restrict__ out,
                             const float* __restrict__ gn_w,
                             const float* __restrict__ gn_b) {
    int idx4 = blockIdx.x*blockDim.x + threadIdx.x;
    size_t base = (size_t)idx4 * 4;
    int co = (int)((base >> 16) & 63);
    int b  = (int)(base >> 22);
    int g  = co >> 2;
    float mean = g_outmr[(b*16+g)*2];
    float rstd = g_outmr[(b*16+g)*2+1];
    float sc = rstd * gn_w[co];
    float sh = gn_b[co] - mean * sc;
    float4 v = *(float4*)&out[base];
    v.x = fmaxf(fmaf(v.x, sc, sh), 0.f);
    v.y = fmaxf(fmaf(v.y, sc, sh), 0.f);
    v.z = fmaxf(fmaf(v.z, sc, sh), 0.f);
    v.w = fmaxf(fmaf(v.w, sc, sh), 0.f);
    *(float4*)&out[base] = v;
}

// ---------------- launch ----------------
extern "C" void kernel_launch(void* const* d_in, const int* in_sizes, int n_in,
                              void* d_out, int out_size) {
    const float* x     = (const float*)d_in[0];
    const float* w_off = (const float*)d_in[1];
    const float* b_off = (const float*)d_in[2];
    const float* gno_w = (const float*)d_in[3];
    const float* gno_b = (const float*)d_in[4];
    const float* w_dsc = (const float*)d_in[5];
    const float* b_dsc = (const float*)d_in[6];
    const float* gn_w  = (const float*)d_in[7];
    const float* gn_b  = (const float*)d_in[8];
    float* out = (float*)d_out;

    cudaFuncSetAttribute(main_kernel, cudaFuncAttributeMaxDynamicSharedMemorySize, SMEM_BYTES);

    conv1_kernel<<<dim3(WW/64, HH/8, BN), 256>>>(x, w_off, b_off);
    offstats_kernel<<<BN*5, 256>>>();
    wprep_kernel<<<(KK*64*64 + 255)/256, 256>>>(w_dsc);
    main_kernel<<<dim3(2, HH, BN), 256, SMEM_BYTES>>>(x, gno_w, gno_b, b_dsc, out);
    outstats_kernel<<<BN*16, 256>>>();
    apply_kernel<<<4096, 512>>>(out, gn_w, gn_b);
}

// round 13
// speedup vs baseline: 2.8337x; 1.1473x over previous
#include <cuda_runtime.h>
#include <cuda_bf16.h>
#include <cuda_fp16.h>
#include <cstdint>
#include <cstring>

#define BN 2
#define CIN 64
#define HH 256
#define WW 256
#define KK 9
#define OC1 10
#define HW (HH*WW)

// ---------------- scratch ----------------
__device__ float g_off[BN*OC1*HW];
__device__ float g_offpart[BN*256*20];    // per-conv1-block (sum,sumsq) x 10 ch
__device__ float g_offstats[BN*5*2];
__device__ __align__(16) __half g_wh[KK*4096];        // [k][swizzled 64co x 64ci] fp16
__device__ __align__(16) __half g_xh[(size_t)BN*HW*64]; // NHWC fp16: [b][y][x][ci]
__device__ float g_part[BN*512*16*2];
__device__ float g_outmr[BN*16*2];

// ---------------- mma helpers (baseline PTX, no 'a' features) ----------------
__device__ __forceinline__ uint32_t smem_u32(const void* p) {
    uint32_t a;
    asm("{ .reg .u64 t; cvta.to.shared.u64 t, %1; cvt.u32.u64 %0, t; }" : "=r"(a) : "l"(p));
    return a;
}
__device__ __forceinline__ void ldsm_x4(uint32_t* r, uint32_t addr) {
    asm volatile("ldmatrix.sync.aligned.m8n8.x4.shared.b16 {%0,%1,%2,%3}, [%4];"
                 : "=r"(r[0]), "=r"(r[1]), "=r"(r[2]), "=r"(r[3]) : "r"(addr));
}
__device__ __forceinline__ void ldsm_x2(uint32_t* r, uint32_t addr) {
    asm volatile("ldmatrix.sync.aligned.m8n8.x2.shared.b16 {%0,%1}, [%2];"
                 : "=r"(r[0]), "=r"(r[1]) : "r"(addr));
}
__device__ __forceinline__ void mma16816h(float* d, const uint32_t* a, const uint32_t* b) {
    asm volatile("mma.sync.aligned.m16n8k16.row.col.f32.f16.f16.f32 "
                 "{%0,%1,%2,%3}, {%4,%5,%6,%7}, {%8,%9}, {%0,%1,%2,%3};"
                 : "+f"(d[0]), "+f"(d[1]), "+f"(d[2]), "+f"(d[3])
                 : "r"(a[0]), "r"(a[1]), "r"(a[2]), "r"(a[3]), "r"(b[0]), "r"(b[1]));
}
__device__ __forceinline__ void cpasync16(uint32_t saddr, const void* gptr) {
    asm volatile("cp.async.ca.shared.global [%0], [%1], 16;" :: "r"(saddr), "l"(gptr) : "memory");
}

// smem layout (dynamic), 2 stages
#define OFF_SH(st)  ((st)*16384)            // [128 pix][64 ci] fp16 swizzled
#define OFF_WH(st)  (32768 + (st)*8192)     // [64 co][64 ci] fp16 swizzled
#define OFF_IY   49152                       // 9*128 floats
#define OFF_SUMS 53760                       // 32 floats
#define SMEM_BYTES 53888

// ---------------- kernel 1: 3x3 conv, 64 -> 10 channels (+ GN stat partials) ----------------
// round-10 proven version: 32-wide tile, 2 ci per barrier pair.
__global__ void conv1_kernel(const float* __restrict__ x,
                             const float* __restrict__ w,
                             const float* __restrict__ bias) {
    int b = blockIdx.z, w0 = blockIdx.x * 32, h0 = blockIdx.y * 8;
    int t = threadIdx.x;
    int tw = t & 31, th = t >> 5;
    __shared__ float xs[2][10][34];
    __shared__ float ws[2][OC1][9];
    __shared__ float red[8][20];
    float acc[OC1];
#pragma unroll
    for (int o = 0; o < OC1; o++) acc[o] = 0.f;

    for (int ci = 0; ci < CIN; ci += 2) {
        for (int i = t; i < 680; i += 256) {
            int half = i >= 340;
            int li = half ? i - 340 : i;
            int r = li / 34, c = li % 34;
            int hy = h0 - 1 + r, wx = w0 - 1 + c;
            float v = 0.f;
            if (hy >= 0 && hy < HH && wx >= 0 && wx < WW)
                v = __ldg(&x[((size_t)(b*CIN + ci + half)*HH + hy)*WW + wx]);
            xs[half][r][c] = v;
        }
        if (t < OC1*9*2) {
            int half = t >= OC1*9;
            int li = half ? t - OC1*9 : t;
            ws[half][li/9][li%9] = __ldg(&w[(li/9)*CIN*9 + (ci + half)*9 + (li%9)]);
        }
        __syncthreads();

#pragma unroll
        for (int half = 0; half < 2; half++) {
            float xv[9];
#pragma unroll
            for (int dy = 0; dy < 3; dy++)
#pragma unroll
                for (int dx = 0; dx < 3; dx++)
                    xv[dy*3+dx] = xs[half][th+dy][tw+dx];
#pragma unroll
            for (int o = 0; o < OC1; o++) {
                float a = acc[o];
#pragma unroll
                for (int tp = 0; tp < 9; tp++) a = fmaf(ws[half][o][tp], xv[tp], a);
                acc[o] = a;
            }
        }
        __syncthreads();
    }
    int lane = t & 31, wid = t >> 5;
#pragma unroll
    for (int o = 0; o < OC1; o++) {
        float v = acc[o] + bias[o];
        g_off[((size_t)(b*OC1 + o)*HH + h0 + th)*WW + w0 + tw] = v;
        float s = v, q = v*v;
#pragma unroll
        for (int m = 16; m; m >>= 1) {
            s += __shfl_xor_sync(0xffffffff, s, m);
            q += __shfl_xor_sync(0xffffffff, q, m);
        }
        if (lane == 0) { red[wid][o*2] = s; red[wid][o*2+1] = q; }
    }
    __syncthreads();
    if (t < 20) {
        float a = 0.f;
#pragma unroll
        for (int wq = 0; wq < 8; wq++) a += red[wq][t];
        int blk = blockIdx.x + 8*blockIdx.y;   // 0..255
        g_offpart[((size_t)(b*256) + blk)*20 + t] = a;
    }
}

// ---------------- kernel 2: reduce offset GN partials ----------------
__global__ void offstats_kernel() {
    int b = blockIdx.x / 5, g = blockIdx.x % 5;
    int t = threadIdx.x;
    float s = 0.f, q = 0.f;
    for (int i = t; i < 256; i += 256) {
        const float* p = g_offpart + ((size_t)(b*256) + i)*20;
        s += p[(2*g)*2]   + p[(2*g+1)*2];
        q += p[(2*g)*2+1] + p[(2*g+1)*2+1];
    }
    __shared__ float rs[256], rq[256];
    rs[t] = s; rq[t] = q; __syncthreads();
    for (int o = 128; o > 0; o >>= 1) {
        if (t < o) { rs[t] += rs[t+o]; rq[t] += rq[t+o]; }
        __syncthreads();
    }
    if (t == 0) {
        float n = (float)(2*HW);
        float mean = rs[0] / n;
        float var = rq[0] / n - mean*mean;
        g_offstats[(b*5+g)*2]   = mean;
        g_offstats[(b*5+g)*2+1] = rsqrtf(var + 1e-5f);
    }
}

// ---------------- kernel 3: w_dsc -> fp16, [k][co][ci] swizzled ----------------
__global__ void wprep_kernel(const float* __restrict__ wdsc) {
    int lin = blockIdx.x*256 + threadIdx.x;       // 9*64*64
    if (lin >= KK*64*64) return;
    int ci = lin & 63, co = (lin >> 6) & 63, k = lin >> 12;
    float v = wdsc[((size_t)(co*64 + ci))*KK + k];
    uint32_t off = (uint32_t)(co*128 + ci*2);
    uint32_t sw = off ^ ((off >> 3) & 0x70);
    *(__half*)((char*)g_wh + (size_t)k*8192 + sw) = __float2half(v);
}

// ---------------- kernel 3b: x NCHW fp32 -> NHWC fp16 (smem transpose) ----------------
// Block: one (b, y) row. 256 threads. Read coalesced along w; write coalesced 16B chunks.
// smem row stride 66 halves (132B): conflict-free transposed writes; reads are
// 4B-aligned u32 (132B stride is NOT 16B aligned, so no vector smem loads here).
__global__ void xprep_kernel(const float* __restrict__ x) {
    int y = blockIdx.x, b = blockIdx.y;
    int t = threadIdx.x;
    __shared__ __half xs[256*66];
    const float* xb = x + (size_t)b*CIN*HW;
#pragma unroll 4
    for (int ci = 0; ci < 64; ci++) {
        float v = __ldg(xb + ((size_t)ci*HH + y)*WW + t);
        xs[t*66 + ci] = __float2half(v);
    }
    __syncthreads();
    char* dst = (char*)(g_xh + ((size_t)b*HW + (size_t)y*WW)*64);
#pragma unroll
    for (int j = 0; j < 8; j++) {
        int c = t + 256*j;            // 16B chunk index within this row's 32KB
        int w = c >> 3, cig = c & 7;
        const uint32_t* src = (const uint32_t*)&xs[w*66];   // 4B-aligned
        uint4 v;
        v.x = src[cig*4 + 0];
        v.y = src[cig*4 + 1];
        v.z = src[cig*4 + 2];
        v.w = src[cig*4 + 3];
        *(uint4*)(dst + (size_t)c*16) = v;
    }
}

// ---------------- kernel 4: pipelined coords + NHWC sampling + fp16 mma.sync GEMM ----------------
// CTA: 128 pixels (N) x 64 co (M), K = 9 taps x 64 ci. 256 threads, 3 CTAs/SM.
__global__ void __launch_bounds__(256, 3)
main_kernel(const float* __restrict__ x,
            const float* __restrict__ gno_w, const float* __restrict__ gno_b,
            const float* __restrict__ b_dsc,
            float* __restrict__ out) {
    extern __shared__ __align__(16) char smem[];
    uint32_t sb = smem_u32(smem);
    float* iy_sh = (float*)(smem + OFF_IY);
    float* sums  = (float*)(smem + OFF_SUMS);

    int t = threadIdx.x, lane = t & 31, wid = t >> 5;
    int b = blockIdx.z, h = blockIdx.y, w0 = blockIdx.x * 128;
    if (t < 32) sums[t] = 0.f;

    // Phase 0: GN+tanh, outward cumsum, clamped iy for 128 pixels x 9 taps
    if (t < 128) {
        int p = t, wg = w0 + p;
        float v[9];
#pragma unroll
        for (int c = 0; c < 9; c++) {
            float raw = g_off[((size_t)(b*OC1 + c)*HH + h)*WW + wg];
            int g = c >> 1;
            float mean = g_offstats[(b*5+g)*2];
            float rstd = g_offstats[(b*5+g)*2+1];
            v[c] = tanhf((raw - mean)*rstd*gno_w[c] + gno_b[c]);
        }
        float cum[9];
        cum[4] = 0.f;
        cum[3] = v[3]; cum[2] = cum[3]+v[2]; cum[1] = cum[2]+v[1]; cum[0] = cum[1]+v[0];
        cum[5] = v[5]; cum[6] = cum[5]+v[6]; cum[7] = cum[6]+v[7]; cum[8] = cum[7]+v[8];
#pragma unroll
        for (int k = 0; k < 9; k++)
            iy_sh[k*128 + p] = fminf(fmaxf((float)h + cum[k], 0.f), 255.f);
    }

    const char* xhb = (const char*)(g_xh + (size_t)b*HW*64);
    int wm = wid & 1, wn = wid >> 1;     // mma warp tiling
    int cig = t & 7;                      // sampling: 8-ci group (16B)

    float acc[2][4][4];
#pragma unroll
    for (int i = 0; i < 2; i++)
#pragma unroll
        for (int j = 0; j < 4; j++)
#pragma unroll
            for (int l = 0; l < 4; l++) acc[i][j][l] = 0.f;

    // item g: pixel = (t>>3) + 32g, ci group = t&7. One 128B NHWC row per 8 lanes.
    auto item_load = [&](int k, int g, uint4& a, uint4& c, float& wy) {
        int pix = (t >> 3) + g*32;
        float iy = iy_sh[k*128 + pix];
        float y0f = floorf(iy);
        wy = iy - y0f;
        int y0 = (int)y0f;
        int y1 = min(y0 + 1, 255);
        int ix = min(max(w0 + pix + k - 4, 0), 255);
        uint32_t o0 = (((uint32_t)y0 << 8) + (uint32_t)ix) << 7;
        uint32_t o1 = (((uint32_t)y1 << 8) + (uint32_t)ix) << 7;
        a = __ldg((const uint4*)(xhb + o0 + (cig << 4)));
        c = __ldg((const uint4*)(xhb + o1 + (cig << 4)));
    };
    auto item_store = [&](int g, uint32_t bufoff, uint4 a, uint4 c, float wy) {
        int pix = (t >> 3) + g*32;
        uint4 r;
        const uint32_t* ap = (const uint32_t*)&a;
        const uint32_t* cp = (const uint32_t*)&c;
        uint32_t* rp = (uint32_t*)&r;
#pragma unroll
        for (int j = 0; j < 4; j++) {
            __half2 ah, ch;
            memcpy(&ah, ap + j, 4); memcpy(&ch, cp + j, 4);
            float2 fa = __half22float2(ah), fc = __half22float2(ch);
            float2 f;
            f.x = fmaf(fc.x - fa.x, wy, fa.x);
            f.y = fmaf(fc.y - fa.y, wy, fa.y);
            __half2 hr = __floats2half2_rn(f.x, f.y);
            memcpy(rp + j, &hr, 4);
        }
        uint32_t off = (uint32_t)(pix*128 + (cig << 4));
        uint32_t sw = off ^ ((off >> 3) & 0x70);
        *(uint4*)(smem + bufoff + sw) = r;
    };
    auto wcopy = [&](int k, uint32_t bufoff) {
        const char* wsrc = (const char*)g_wh + (size_t)k*8192 + t*32;
        cpasync16(sb + bufoff + t*32,      wsrc);
        cpasync16(sb + bufoff + t*32 + 16, wsrc + 16);
        asm volatile("cp.async.commit_group;" ::: "memory");
    };
    auto mma_kt = [&](int kt, uint32_t soff, uint32_t woff) {
        uint32_t af[2][4];
#pragma unroll
        for (int mt = 0; mt < 2; mt++) {
            uint32_t row = (uint32_t)(wm*32 + mt*16 + (lane & 15));
            uint32_t c16 = (uint32_t)(kt*2 + (lane >> 4));
            uint32_t off = row*128 + c16*16;
            uint32_t sw = off ^ ((off >> 3) & 0x70);
            ldsm_x4(af[mt], sb + woff + sw);
        }
        uint32_t bf[4][2];
#pragma unroll
        for (int nt = 0; nt < 4; nt++) {
            uint32_t row = (uint32_t)(wn*32 + nt*8 + (lane & 7));
            uint32_t c16 = (uint32_t)(kt*2 + ((lane >> 3) & 1));
            uint32_t off = row*128 + c16*16;
            uint32_t sw = off ^ ((off >> 3) & 0x70);
            ldsm_x2(bf[nt], sb + soff + sw);
        }
#pragma unroll
        for (int mt = 0; mt < 2; mt++)
#pragma unroll
            for (int nt = 0; nt < 4; nt++)
                mma16816h(acc[mt][nt], af[mt], bf[nt]);
    };

    // ---- prologue: W0 + sample tap 0 into stage 0 ----
    wcopy(0, OFF_WH(0));
    __syncthreads();           // iy_sh visible
#pragma unroll
    for (int g = 0; g < 4; g++) {
        uint4 a, c; float wy;
        item_load(0, g, a, c, wy);
        item_store(g, OFF_SH(0), a, c, wy);
    }
    asm volatile("cp.async.wait_group 0;" ::: "memory");
    __syncthreads();           // sbuf0 + wbuf0 ready

    // ---- main loop: mma tap k, sample tap k+1, one barrier per tap ----
#pragma unroll 1
    for (int k = 0; k < KK; k++) {
        int st = k & 1, ns = st ^ 1;
        bool pf = (k < KK-1);
        uint32_t soff = OFF_SH(st), woff = OFF_WH(st);

        if (pf) wcopy(k+1, OFF_WH(ns));

#pragma unroll
        for (int g = 0; g < 4; g++) {
            uint4 a, c; float wy = 0.f;
            if (pf) item_load(k+1, g, a, c, wy);   // LDG latency hides under mma below
            mma_kt(g, soff, woff);
            if (pf) item_store(g, OFF_SH(ns), a, c, wy);
        }

        if (pf) { asm volatile("cp.async.wait_group 0;" ::: "memory"); }
        __syncthreads();
    }

    // ---- epilogue: bias, store, GN partial sums ----
    {
        int q = lane >> 2;                    // co row within tile
        int pp = (lane & 3) * 2;              // pixel pair
        float s_l[2][2] = {{0.f,0.f},{0.f,0.f}}, q_l[2][2] = {{0.f,0.f},{0.f,0.f}};
#pragma unroll
        for (int mt = 0; mt < 2; mt++) {
            int cog = wm*32 + mt*16 + q;
            float b0 = __ldg(b_dsc + cog);
            float b1 = __ldg(b_dsc + cog + 8);
#pragma unroll
            for (int nt = 0; nt < 4; nt++) {
                int pix = wn*32 + nt*8 + pp;
                float v0 = acc[mt][nt][0] + b0;
                float v1 = acc[mt][nt][1] + b0;
                float v2 = acc[mt][nt][2] + b1;
                float v3 = acc[mt][nt][3] + b1;
                *(float2*)&out[((size_t)(b*64 + cog)*HH + h)*WW + w0 + pix]     = make_float2(v0, v1);
                *(float2*)&out[((size_t)(b*64 + cog + 8)*HH + h)*WW + w0 + pix] = make_float2(v2, v3);
                s_l[mt][0] += v0 + v1; q_l[mt][0] += v0*v0 + v1*v1;
                s_l[mt][1] += v2 + v3; q_l[mt][1] += v2*v2 + v3*v3;
            }
        }
#pragma unroll
        for (int mt = 0; mt < 2; mt++)
#pragma unroll
            for (int hf = 0; hf < 2; hf++) {
#pragma unroll
                for (int m = 1; m <= 2; m <<= 1) {
                    s_l[mt][hf] += __shfl_xor_sync(0xffffffff, s_l[mt][hf], m);
                    q_l[mt][hf] += __shfl_xor_sync(0xffffffff, q_l[mt][hf], m);
                }
                if ((lane & 3) == 0) {
                    int grp = (wm*32 + mt*16 + hf*8 + q) >> 2;
                    atomicAdd(&sums[2*grp],   s_l[mt][hf]);
                    atomicAdd(&sums[2*grp+1], q_l[mt][hf]);
                }
            }
    }
    __syncthreads();
    if (t < 32) {
        int bw = blockIdx.x + 2*h;     // 0..511 within batch
        g_part[((size_t)(b*512 + bw)*16 + (t >> 1))*2 + (t & 1)] = sums[t];
    }
}

// ---------------- kernel 5: reduce out-GN partials ----------------
__global__ void outstats_kernel() {
    int b = blockIdx.x >> 4, g = blockIdx.x & 15;
    int t = threadIdx.x;
    float s = 0.f, q = 0.f;
    for (int i = t; i < 512; i += 256) {
        size_t idx = ((size_t)(b*512 + i)*16 + g)*2;
        s += g_part[idx];
        q += g_part[idx + 1];
    }
    __shared__ float rs[256], rq[256];
    rs[t] = s; rq[t] = q; __syncthreads();
    for (int o = 128; o > 0; o >>= 1) {
        if (t < o) { rs[t] += rs[t+o]; rq[t] += rq[t+o]; }
        __syncthreads();
    }
    if (t == 0) {
        float n = 4.f * HW;
        float mean = rs[0] / n;
        float var = rq[0] / n - mean*mean;
        g_outmr[(b*16+g)*2]   = mean;
        g_outmr[(b*16+g)*2+1] = rsqrtf(var + 1e-5f);
    }
}

// ---------------- kernel 6: apply GN + ReLU ----------------
__global__ void apply_kernel(float* __restrict__ out,
                             const float* __restrict__ gn_w,
                             const float* __restrict__ gn_b) {
    int idx4 = blockIdx.x*blockDim.x + threadIdx.x;
    size_t base = (size_t)idx4 * 4;
    int co = (int)((base >> 16) & 63);
    int b  = (int)(base >> 22);
    int g  = co >> 2;
    float mean = g_outmr[(b*16+g)*2];
    float rstd = g_outmr[(b*16+g)*2+1];
    float sc = rstd * gn_w[co];
    float sh = gn_b[co] - mean * sc;
    float4 v = *(float4*)&out[base];
    v.x = fmaxf(fmaf(v.x, sc, sh), 0.f);
    v.y = fmaxf(fmaf(v.y, sc, sh), 0.f);
    v.z = fmaxf(fmaf(v.z, sc, sh), 0.f);
    v.w = fmaxf(fmaf(v.w, sc, sh), 0.f);
    *(float4*)&out[base] = v;
}

// ---------------- launch ----------------
extern "C" void kernel_launch(void* const* d_in, const int* in_sizes, int n_in,
                              void* d_out, int out_size) {
    const float* x     = (const float*)d_in[0];
    const float* w_off = (const float*)d_in[1];
    const float* b_off = (const float*)d_in[2];
    const float* gno_w = (const float*)d_in[3];
    const float* gno_b = (const float*)d_in[4];
    const float* w_dsc = (const float*)d_in[5];
    const float* b_dsc = (const float*)d_in[6];
    const float* gn_w  = (const float*)d_in[7];
    const float* gn_b  = (const float*)d_in[8];
    float* out = (float*)d_out;

    cudaFuncSetAttribute(main_kernel, cudaFuncAttributeMaxDynamicSharedMemorySize, SMEM_BYTES);

    conv1_kernel<<<dim3(WW/32, HH/8, BN), 256>>>(x, w_off, b_off);
    xprep_kernel<<<dim3(HH, BN), 256>>>(x);
    offstats_kernel<<<BN*5, 256>>>();
    wprep_kernel<<<(KK*64*64 + 255)/256, 256>>>(w_dsc);
    main_kernel<<<dim3(2, HH, BN), 256, SMEM_BYTES>>>(x, gno_w, gno_b, b_dsc, out);
    outstats_kernel<<<BN*16, 256>>>();
    apply_kernel<<<4096, 512>>>(out, gn_w, gn_b);
}

// round 14
// speedup vs baseline: 4.0325x; 1.4230x over previous
#include <cuda_runtime.h>
#include <cuda_bf16.h>
#include <cuda_fp16.h>
#include <cstdint>
#include <cstring>

#define BN 2
#define CIN 64
#define HH 256
#define WW 256
#define KK 9
#define OC1 10
#define HW (HH*WW)

// ---------------- scratch ----------------
__device__ float g_off[BN*OC1*HW];
__device__ float g_offpart[BN*512*20];    // per-conv1-block (sum,sumsq) x 10 ch
__device__ float g_offstats[BN*5*2];
__device__ __align__(16) __half g_wh[KK*4096];         // [k][swizzled 64co x 64ci] fp16 (dsc conv)
__device__ __align__(16) __half g_wc1[KK*1024];        // [k][swizzled 16co x 64ci] fp16 (offset conv)
__device__ __align__(16) __half g_xh[(size_t)BN*HW*64]; // NHWC fp16: [b][y][x][ci]
__device__ float g_part[BN*512*16*2];
__device__ float g_outmr[BN*16*2];

// ---------------- mma helpers (baseline PTX, no 'a' features) ----------------
__device__ __forceinline__ uint32_t smem_u32(const void* p) {
    uint32_t a;
    asm("{ .reg .u64 t; cvta.to.shared.u64 t, %1; cvt.u32.u64 %0, t; }" : "=r"(a) : "l"(p));
    return a;
}
__device__ __forceinline__ void ldsm_x4(uint32_t* r, uint32_t addr) {
    asm volatile("ldmatrix.sync.aligned.m8n8.x4.shared.b16 {%0,%1,%2,%3}, [%4];"
                 : "=r"(r[0]), "=r"(r[1]), "=r"(r[2]), "=r"(r[3]) : "r"(addr));
}
__device__ __forceinline__ void ldsm_x2(uint32_t* r, uint32_t addr) {
    asm volatile("ldmatrix.sync.aligned.m8n8.x2.shared.b16 {%0,%1}, [%2];"
                 : "=r"(r[0]), "=r"(r[1]) : "r"(addr));
}
__device__ __forceinline__ void mma16816h(float* d, const uint32_t* a, const uint32_t* b) {
    asm volatile("mma.sync.aligned.m16n8k16.row.col.f32.f16.f16.f32 "
                 "{%0,%1,%2,%3}, {%4,%5,%6,%7}, {%8,%9}, {%0,%1,%2,%3};"
                 : "+f"(d[0]), "+f"(d[1]), "+f"(d[2]), "+f"(d[3])
                 : "r"(a[0]), "r"(a[1]), "r"(a[2]), "r"(a[3]), "r"(b[0]), "r"(b[1]));
}
__device__ __forceinline__ void cpasync16(uint32_t saddr, const void* gptr) {
    asm volatile("cp.async.ca.shared.global [%0], [%1], 16;" :: "r"(saddr), "l"(gptr) : "memory");
}

// smem layout for main_kernel (dynamic), 2 stages
#define OFF_SH(st)  ((st)*16384)            // [128 pix][64 ci] fp16 swizzled
#define OFF_WH(st)  (32768 + (st)*8192)     // [64 co][64 ci] fp16 swizzled
#define OFF_IY   49152                       // 9*128 floats
#define OFF_SUMS 53760                       // 32 floats
#define SMEM_BYTES 53888

// ---------------- kernel 1: x NCHW fp32 -> NHWC fp16 (smem transpose) ----------------
__global__ void xprep_kernel(const float* __restrict__ x) {
    int y = blockIdx.x, b = blockIdx.y;
    int t = threadIdx.x;
    __shared__ __half xs[256*66];
    const float* xb = x + (size_t)b*CIN*HW;
#pragma unroll 4
    for (int ci = 0; ci < 64; ci++) {
        float v = __ldg(xb + ((size_t)ci*HH + y)*WW + t);
        xs[t*66 + ci] = __float2half(v);
    }
    __syncthreads();
    char* dst = (char*)(g_xh + ((size_t)b*HW + (size_t)y*WW)*64);
#pragma unroll
    for (int j = 0; j < 8; j++) {
        int c = t + 256*j;
        int w = c >> 3, cig = c & 7;
        const uint32_t* src = (const uint32_t*)&xs[w*66];   // 4B-aligned
        uint4 v;
        v.x = src[cig*4 + 0];
        v.y = src[cig*4 + 1];
        v.z = src[cig*4 + 2];
        v.w = src[cig*4 + 3];
        *(uint4*)(dst + (size_t)c*16) = v;
    }
}

// ---------------- kernel 2a: w_dsc -> fp16, [k][64co][64ci] swizzled ----------------
__global__ void wprep_kernel(const float* __restrict__ wdsc) {
    int lin = blockIdx.x*256 + threadIdx.x;       // 9*64*64
    if (lin >= KK*64*64) return;
    int ci = lin & 63, co = (lin >> 6) & 63, k = lin >> 12;
    float v = wdsc[((size_t)(co*64 + ci))*KK + k];
    uint32_t off = (uint32_t)(co*128 + ci*2);
    uint32_t sw = off ^ ((off >> 3) & 0x70);
    *(__half*)((char*)g_wh + (size_t)k*8192 + sw) = __float2half(v);
}

// ---------------- kernel 2b: w_off -> fp16, [k][16co][64ci] swizzled (co>=10 zero) ----------------
__global__ void wprepc1_kernel(const float* __restrict__ woff) {
    int lin = blockIdx.x*256 + threadIdx.x;       // 9*16*64
    if (lin >= KK*16*64) return;
    int ci = lin & 63, co = (lin >> 6) & 15, k = lin >> 10;
    float v = (co < OC1) ? woff[((size_t)(co*64 + ci))*9 + k] : 0.f;
    uint32_t off = (uint32_t)(co*128 + ci*2);
    uint32_t sw = off ^ ((off >> 3) & 0x70);
    *(__half*)((char*)g_wc1 + (size_t)k*2048 + sw) = __float2half(v);
}

// ---------------- kernel 3: 3x3 offset conv via mma (16co x 128pix, K=576) ----------------
// Pipelined like main_kernel; taps are fixed (dy,dx) shifts; zero padding OOB.
__global__ void __launch_bounds__(256, 4)
conv1g_kernel(const float* __restrict__ b_off) {
    __shared__ __align__(16) char smem[36864];   // S 2x16KB + W 2x2KB
    __shared__ float sums20[20];
    uint32_t sb = smem_u32(smem);
#define C1_SH(st) ((st)*16384)
#define C1_WH(st) (32768 + (st)*2048)

    int t = threadIdx.x, lane = t & 31, wid = t >> 5;
    int b = blockIdx.z, h = blockIdx.y, w0 = blockIdx.x * 128;
    if (t < 20) sums20[t] = 0.f;

    const char* xhb = (const char*)(g_xh + (size_t)b*HW*64);
    int cig = t & 7;

    float acc[2][4];
#pragma unroll
    for (int i = 0; i < 2; i++)
#pragma unroll
        for (int j = 0; j < 4; j++) acc[i][j] = 0.f;

    auto item_load = [&](int k, int g, uint4& a) {
        int pix = (t >> 3) + g*32;
        int y = h + (k/3) - 1;
        int ix = w0 + pix + (k%3) - 1;
        if (y < 0 || y > 255 || ix < 0 || ix > 255) {
            a = make_uint4(0u, 0u, 0u, 0u);
        } else {
            uint32_t o = (((uint32_t)y << 8) + (uint32_t)ix) << 7;
            a = __ldg((const uint4*)(xhb + o + (cig << 4)));
        }
    };
    auto item_store = [&](int g, uint32_t bufoff, uint4 a) {
        int pix = (t >> 3) + g*32;
        uint32_t off = (uint32_t)(pix*128 + (cig << 4));
        uint32_t sw = off ^ ((off >> 3) & 0x70);
        *(uint4*)(smem + bufoff + sw) = a;
    };
    auto wcopy = [&](int k, uint32_t bufoff) {
        if (t < 128)
            cpasync16(sb + bufoff + t*16, (const char*)g_wc1 + (size_t)k*2048 + t*16);
        asm volatile("cp.async.commit_group;" ::: "memory");
    };
    auto mma_tap = [&](uint32_t soff, uint32_t woff) {
#pragma unroll
        for (int kt = 0; kt < 4; kt++) {
            uint32_t af[4];
            {
                uint32_t row = (uint32_t)(lane & 15);
                uint32_t c16 = (uint32_t)(kt*2 + (lane >> 4));
                uint32_t off = row*128 + c16*16;
                uint32_t sw = off ^ ((off >> 3) & 0x70);
                ldsm_x4(af, sb + woff + sw);
            }
#pragma unroll
            for (int nt = 0; nt < 2; nt++) {
                uint32_t bf[2];
                uint32_t row = (uint32_t)(wid*16 + nt*8 + (lane & 7));
                uint32_t c16 = (uint32_t)(kt*2 + ((lane >> 3) & 1));
                uint32_t off = row*128 + c16*16;
                uint32_t sw = off ^ ((off >> 3) & 0x70);
                ldsm_x2(bf, sb + soff + sw);
                mma16816h(acc[nt], af, bf);
            }
        }
    };

    // prologue: tap 0
    wcopy(0, C1_WH(0));
#pragma unroll
    for (int g = 0; g < 4; g++) {
        uint4 a;
        item_load(0, g, a);
        item_store(g, C1_SH(0), a);
    }
    asm volatile("cp.async.wait_group 0;" ::: "memory");
    __syncthreads();

#pragma unroll 1
    for (int k = 0; k < KK; k++) {
        int st = k & 1, ns = st ^ 1;
        bool pf = (k < KK-1);
        if (pf) wcopy(k+1, C1_WH(ns));
#pragma unroll
        for (int g = 0; g < 4; g++) {
            uint4 a;
            if (pf) item_load(k+1, g, a);
            if (g == 0) mma_tap(C1_SH(st), C1_WH(st));   // all 4 ksteps in one shot
            if (pf) item_store(g, C1_SH(ns), a);
        }
        if (pf) { asm volatile("cp.async.wait_group 0;" ::: "memory"); }
        __syncthreads();
    }

    // epilogue: bias, store g_off (co<10), GN partials
    {
        int q = lane >> 2;                 // co row 0..7 (and q+8)
        int pp = (lane & 3) * 2;
        float b0 = (q < OC1) ? __ldg(b_off + q) : 0.f;
        float b1 = (q + 8 < OC1) ? __ldg(b_off + q + 8) : 0.f;
        float s0 = 0.f, q0 = 0.f, s1 = 0.f, q1 = 0.f;
#pragma unroll
        for (int nt = 0; nt < 2; nt++) {
            int pix = wid*16 + nt*8 + pp;
            float v0 = acc[nt][0] + b0;
            float v1 = acc[nt][1] + b0;
            float v2 = acc[nt][2] + b1;
            float v3 = acc[nt][3] + b1;
            if (q < OC1) {
                *(float2*)&g_off[((size_t)(b*OC1 + q)*HH + h)*WW + w0 + pix] = make_float2(v0, v1);
                s0 += v0 + v1; q0 += v0*v0 + v1*v1;
            }
            if (q + 8 < OC1) {
                *(float2*)&g_off[((size_t)(b*OC1 + q + 8)*HH + h)*WW + w0 + pix] = make_float2(v2, v3);
                s1 += v2 + v3; q1 += v2*v2 + v3*v3;
            }
        }
#pragma unroll
        for (int m = 1; m <= 2; m <<= 1) {
            s0 += __shfl_xor_sync(0xffffffff, s0, m);
            q0 += __shfl_xor_sync(0xffffffff, q0, m);
            s1 += __shfl_xor_sync(0xffffffff, s1, m);
            q1 += __shfl_xor_sync(0xffffffff, q1, m);
        }
        if ((lane & 3) == 0) {
            if (q < OC1)     { atomicAdd(&sums20[q*2], s0);       atomicAdd(&sums20[q*2+1], q0); }
            if (q + 8 < OC1) { atomicAdd(&sums20[(q+8)*2], s1);   atomicAdd(&sums20[(q+8)*2+1], q1); }
        }
    }
    __syncthreads();
    if (t < 20) {
        int blk = blockIdx.x + 2*h;    // 0..511
        g_offpart[((size_t)(b*512) + blk)*20 + t] = sums20[t];
    }
}

// ---------------- kernel 4: reduce offset GN partials ----------------
__global__ void offstats_kernel() {
    int b = blockIdx.x / 5, g = blockIdx.x % 5;
    int t = threadIdx.x;
    float s = 0.f, q = 0.f;
    for (int i = t; i < 512; i += 256) {
        const float* p = g_offpart + ((size_t)(b*512) + i)*20;
        s += p[(2*g)*2]   + p[(2*g+1)*2];
        q += p[(2*g)*2+1] + p[(2*g+1)*2+1];
    }
    __shared__ float rs[256], rq[256];
    rs[t] = s; rq[t] = q; __syncthreads();
    for (int o = 128; o > 0; o >>= 1) {
        if (t < o) { rs[t] += rs[t+o]; rq[t] += rq[t+o]; }
        __syncthreads();
    }
    if (t == 0) {
        float n = (float)(2*HW);
        float mean = rs[0] / n;
        float var = rq[0] / n - mean*mean;
        g_offstats[(b*5+g)*2]   = mean;
        g_offstats[(b*5+g)*2+1] = rsqrtf(var + 1e-5f);
    }
}

// ---------------- kernel 5: pipelined coords + NHWC sampling + fp16 mma.sync GEMM ----------------
__global__ void __launch_bounds__(256, 3)
main_kernel(const float* __restrict__ x,
            const float* __restrict__ gno_w, const float* __restrict__ gno_b,
            const float* __restrict__ b_dsc,
            float* __restrict__ out) {
    extern __shared__ __align__(16) char smem[];
    uint32_t sb = smem_u32(smem);
    float* iy_sh = (float*)(smem + OFF_IY);
    float* sums  = (float*)(smem + OFF_SUMS);

    int t = threadIdx.x, lane = t & 31, wid = t >> 5;
    int b = blockIdx.z, h = blockIdx.y, w0 = blockIdx.x * 128;
    if (t < 32) sums[t] = 0.f;

    // Phase 0: GN+tanh, outward cumsum, clamped iy for 128 pixels x 9 taps
    if (t < 128) {
        int p = t, wg = w0 + p;
        float v[9];
#pragma unroll
        for (int c = 0; c < 9; c++) {
            float raw = g_off[((size_t)(b*OC1 + c)*HH + h)*WW + wg];
            int g = c >> 1;
            float mean = g_offstats[(b*5+g)*2];
            float rstd = g_offstats[(b*5+g)*2+1];
            v[c] = tanhf((raw - mean)*rstd*gno_w[c] + gno_b[c]);
        }
        float cum[9];
        cum[4] = 0.f;
        cum[3] = v[3]; cum[2] = cum[3]+v[2]; cum[1] = cum[2]+v[1]; cum[0] = cum[1]+v[0];
        cum[5] = v[5]; cum[6] = cum[5]+v[6]; cum[7] = cum[6]+v[7]; cum[8] = cum[7]+v[8];
#pragma unroll
        for (int k = 0; k < 9; k++)
            iy_sh[k*128 + p] = fminf(fmaxf((float)h + cum[k], 0.f), 255.f);
    }

    const char* xhb = (const char*)(g_xh + (size_t)b*HW*64);
    int wm = wid & 1, wn = wid >> 1;     // mma warp tiling
    int cig = t & 7;                      // sampling: 8-ci group (16B)

    float acc[2][4][4];
#pragma unroll
    for (int i = 0; i < 2; i++)
#pragma unroll
        for (int j = 0; j < 4; j++)
#pragma unroll
            for (int l = 0; l < 4; l++) acc[i][j][l] = 0.f;

    auto item_load = [&](int k, int g, uint4& a, uint4& c, float& wy) {
        int pix = (t >> 3) + g*32;
        float iy = iy_sh[k*128 + pix];
        float y0f = floorf(iy);
        wy = iy - y0f;
        int y0 = (int)y0f;
        int y1 = min(y0 + 1, 255);
        int ix = min(max(w0 + pix + k - 4, 0), 255);
        uint32_t o0 = (((uint32_t)y0 << 8) + (uint32_t)ix) << 7;
        uint32_t o1 = (((uint32_t)y1 << 8) + (uint32_t)ix) << 7;
        a = __ldg((const uint4*)(xhb + o0 + (cig << 4)));
        c = __ldg((const uint4*)(xhb + o1 + (cig << 4)));
    };
    auto item_store = [&](int g, uint32_t bufoff, uint4 a, uint4 c, float wy) {
        int pix = (t >> 3) + g*32;
        uint4 r;
        const uint32_t* ap = (const uint32_t*)&a;
        const uint32_t* cp = (const uint32_t*)&c;
        uint32_t* rp = (uint32_t*)&r;
#pragma unroll
        for (int j = 0; j < 4; j++) {
            __half2 ah, ch;
            memcpy(&ah, ap + j, 4); memcpy(&ch, cp + j, 4);
            float2 fa = __half22float2(ah), fc = __half22float2(ch);
            float2 f;
            f.x = fmaf(fc.x - fa.x, wy, fa.x);
            f.y = fmaf(fc.y - fa.y, wy, fa.y);
            __half2 hr = __floats2half2_rn(f.x, f.y);
            memcpy(rp + j, &hr, 4);
        }
        uint32_t off = (uint32_t)(pix*128 + (cig << 4));
        uint32_t sw = off ^ ((off >> 3) & 0x70);
        *(uint4*)(smem + bufoff + sw) = r;
    };
    auto wcopy = [&](int k, uint32_t bufoff) {
        const char* wsrc = (const char*)g_wh + (size_t)k*8192 + t*32;
        cpasync16(sb + bufoff + t*32,      wsrc);
        cpasync16(sb + bufoff + t*32 + 16, wsrc + 16);
        asm volatile("cp.async.commit_group;" ::: "memory");
    };
    auto mma_kt = [&](int kt, uint32_t soff, uint32_t woff) {
        uint32_t af[2][4];
#pragma unroll
        for (int mt = 0; mt < 2; mt++) {
            uint32_t row = (uint32_t)(wm*32 + mt*16 + (lane & 15));
            uint32_t c16 = (uint32_t)(kt*2 + (lane >> 4));
            uint32_t off = row*128 + c16*16;
            uint32_t sw = off ^ ((off >> 3) & 0x70);
            ldsm_x4(af[mt], sb + woff + sw);
        }
        uint32_t bf[4][2];
#pragma unroll
        for (int nt = 0; nt < 4; nt++) {
            uint32_t row = (uint32_t)(wn*32 + nt*8 + (lane & 7));
            uint32_t c16 = (uint32_t)(kt*2 + ((lane >> 3) & 1));
            uint32_t off = row*128 + c16*16;
            uint32_t sw = off ^ ((off >> 3) & 0x70);
            ldsm_x2(bf[nt], sb + soff + sw);
        }
#pragma unroll
        for (int mt = 0; mt < 2; mt++)
#pragma unroll
            for (int nt = 0; nt < 4; nt++)
                mma16816h(acc[mt][nt], af[mt], bf[nt]);
    };

    // prologue
    wcopy(0, OFF_WH(0));
    __syncthreads();
#pragma unroll
    for (int g = 0; g < 4; g++) {
        uint4 a, c; float wy;
        item_load(0, g, a, c, wy);
        item_store(g, OFF_SH(0), a, c, wy);
    }
    asm volatile("cp.async.wait_group 0;" ::: "memory");
    __syncthreads();

#pragma unroll 1
    for (int k = 0; k < KK; k++) {
        int st = k & 1, ns = st ^ 1;
        bool pf = (k < KK-1);
        uint32_t soff = OFF_SH(st), woff = OFF_WH(st);

        if (pf) wcopy(k+1, OFF_WH(ns));

#pragma unroll
        for (int g = 0; g < 4; g++) {
            uint4 a, c; float wy = 0.f;
            if (pf) item_load(k+1, g, a, c, wy);
            mma_kt(g, soff, woff);
            if (pf) item_store(g, OFF_SH(ns), a, c, wy);
        }

        if (pf) { asm volatile("cp.async.wait_group 0;" ::: "memory"); }
        __syncthreads();
    }

    // epilogue: bias, store, GN partial sums
    {
        int q = lane >> 2;
        int pp = (lane & 3) * 2;
        float s_l[2][2] = {{0.f,0.f},{0.f,0.f}}, q_l[2][2] = {{0.f,0.f},{0.f,0.f}};
#pragma unroll
        for (int mt = 0; mt < 2; mt++) {
            int cog = wm*32 + mt*16 + q;
            float b0 = __ldg(b_dsc + cog);
            float b1 = __ldg(b_dsc + cog + 8);
#pragma unroll
            for (int nt = 0; nt < 4; nt++) {
                int pix = wn*32 + nt*8 + pp;
                float v0 = acc[mt][nt][0] + b0;
                float v1 = acc[mt][nt][1] + b0;
                float v2 = acc[mt][nt][2] + b1;
                float v3 = acc[mt][nt][3] + b1;
                *(float2*)&out[((size_t)(b*64 + cog)*HH + h)*WW + w0 + pix]     = make_float2(v0, v1);
                *(float2*)&out[((size_t)(b*64 + cog + 8)*HH + h)*WW + w0 + pix] = make_float2(v2, v3);
                s_l[mt][0] += v0 + v1; q_l[mt][0] += v0*v0 + v1*v1;
                s_l[mt][1] += v2 + v3; q_l[mt][1] += v2*v2 + v3*v3;
            }
        }
#pragma unroll
        for (int mt = 0; mt < 2; mt++)
#pragma unroll
            for (int hf = 0; hf < 2; hf++) {
#pragma unroll
                for (int m = 1; m <= 2; m <<= 1) {
                    s_l[mt][hf] += __shfl_xor_sync(0xffffffff, s_l[mt][hf], m);
                    q_l[mt][hf] += __shfl_xor_sync(0xffffffff, q_l[mt][hf], m);
                }
                if ((lane & 3) == 0) {
                    int grp = (wm*32 + mt*16 + hf*8 + q) >> 2;
                    atomicAdd(&sums[2*grp],   s_l[mt][hf]);
                    atomicAdd(&sums[2*grp+1], q_l[mt][hf]);
                }
            }
    }
    __syncthreads();
    if (t < 32) {
        int bw = blockIdx.x + 2*h;
        g_part[((size_t)(b*512 + bw)*16 + (t >> 1))*2 + (t & 1)] = sums[t];
    }
}

// ---------------- kernel 6: reduce out-GN partials ----------------
__global__ void outstats_kernel() {
    int b = blockIdx.x >> 4, g = blockIdx.x & 15;
    int t = threadIdx.x;
    float s = 0.f, q = 0.f;
    for (int i = t; i < 512; i += 256) {
        size_t idx = ((size_t)(b*512 + i)*16 + g)*2;
        s += g_part[idx];
        q += g_part[idx + 1];
    }
    __shared__ float rs[256], rq[256];
    rs[t] = s; rq[t] = q; __syncthreads();
    for (int o = 128; o > 0; o >>= 1) {
        if (t < o) { rs[t] += rs[t+o]; rq[t] += rq[t+o]; }
        __syncthreads();
    }
    if (t == 0) {
        float n = 4.f * HW;
        float mean = rs[0] / n;
        float var = rq[0] / n - mean*mean;
        g_outmr[(b*16+g)*2]   = mean;
        g_outmr[(b*16+g)*2+1] = rsqrtf(var + 1e-5f);
    }
}

// ---------------- kernel 7: apply GN + ReLU ----------------
__global__ void apply_kernel(float* __restrict__ out,
                             const float* __restrict__ gn_w,
                             const float* __restrict__ gn_b) {
    int idx4 = blockIdx.x*blockDim.x + threadIdx.x;
    size_t base = (size_t)idx4 * 4;
    int co = (int)((base >> 16) & 63);
    int b  = (int)(base >> 22);
    int g  = co >> 2;
    float mean = g_outmr[(b*16+g)*2];
    float rstd = g_outmr[(b*16+g)*2+1];
    float sc = rstd * gn_w[co];
    float sh = gn_b[co] - mean * sc;
    float4 v = *(float4*)&out[base];
    v.x = fmaxf(fmaf(v.x, sc, sh), 0.f);
    v.y = fmaxf(fmaf(v.y, sc, sh), 0.f);
    v.z = fmaxf(fmaf(v.z, sc, sh), 0.f);
    v.w = fmaxf(fmaf(v.w, sc, sh), 0.f);
    *(float4*)&out[base] = v;
}

// ---------------- launch ----------------
extern "C" void kernel_launch(void* const* d_in, const int* in_sizes, int n_in,
                              void* d_out, int out_size) {
    const float* x     = (const float*)d_in[0];
    const float* w_off = (const float*)d_in[1];
    const float* b_off = (const float*)d_in[2];
    const float* gno_w = (const float*)d_in[3];
    const float* gno_b = (const float*)d_in[4];
    const float* w_dsc = (const float*)d_in[5];
    const float* b_dsc = (const float*)d_in[6];
    const float* gn_w  = (const float*)d_in[7];
    const float* gn_b  = (const float*)d_in[8];
    float* out = (float*)d_out;

    cudaFuncSetAttribute(main_kernel, cudaFuncAttributeMaxDynamicSharedMemorySize, SMEM_BYTES);

    xprep_kernel<<<dim3(HH, BN), 256>>>(x);
    wprep_kernel<<<(KK*64*64 + 255)/256, 256>>>(w_dsc);
    wprepc1_kernel<<<(KK*16*64 + 255)/256, 256>>>(w_off);
    conv1g_kernel<<<dim3(2, HH, BN), 256>>>(b_off);
    offstats_kernel<<<BN*5, 256>>>();
    main_kernel<<<dim3(2, HH, BN), 256, SMEM_BYTES>>>(x, gno_w, gno_b, b_dsc, out);
    outstats_kernel<<<BN*16, 256>>>();
    apply_kernel<<<4096, 512>>>(out, gn_w, gn_b);
}

// round 15
// speedup vs baseline: 4.1464x; 1.0282x over previous
#include <cuda_runtime.h>
#include <cuda_bf16.h>
#include <cuda_fp16.h>
#include <cstdint>
#include <cstring>

#define BN 2
#define CIN 64
#define HH 256
#define WW 256
#define KK 9
#define OC1 10
#define HW (HH*WW)

// ---------------- scratch ----------------
__device__ float g_off[BN*OC1*HW];
__device__ float g_offpart[BN*512*20];    // per-conv1-block (sum,sumsq) x 10 ch
__device__ float g_offstats[BN*5*2];
__device__ __align__(16) __half g_wh[KK*4096];         // [k][swizzled 64co x 64ci] fp16 (dsc conv)
__device__ __align__(16) __half g_wc1[KK*1024];        // [k][swizzled 16co x 64ci] fp16 (offset conv)
__device__ __align__(16) __half g_xh[(size_t)BN*HW*64]; // NHWC fp16: [b][y][x][ci]
__device__ float g_part[BN*512*16*2];
__device__ float g_outmr[BN*16*2];

// ---------------- mma helpers (baseline PTX, no 'a' features) ----------------
__device__ __forceinline__ uint32_t smem_u32(const void* p) {
    uint32_t a;
    asm("{ .reg .u64 t; cvta.to.shared.u64 t, %1; cvt.u32.u64 %0, t; }" : "=r"(a) : "l"(p));
    return a;
}
__device__ __forceinline__ void ldsm_x4(uint32_t* r, uint32_t addr) {
    asm volatile("ldmatrix.sync.aligned.m8n8.x4.shared.b16 {%0,%1,%2,%3}, [%4];"
                 : "=r"(r[0]), "=r"(r[1]), "=r"(r[2]), "=r"(r[3]) : "r"(addr));
}
__device__ __forceinline__ void ldsm_x2(uint32_t* r, uint32_t addr) {
    asm volatile("ldmatrix.sync.aligned.m8n8.x2.shared.b16 {%0,%1}, [%2];"
                 : "=r"(r[0]), "=r"(r[1]) : "r"(addr));
}
__device__ __forceinline__ void mma16816h(float* d, const uint32_t* a, const uint32_t* b) {
    asm volatile("mma.sync.aligned.m16n8k16.row.col.f32.f16.f16.f32 "
                 "{%0,%1,%2,%3}, {%4,%5,%6,%7}, {%8,%9}, {%0,%1,%2,%3};"
                 : "+f"(d[0]), "+f"(d[1]), "+f"(d[2]), "+f"(d[3])
                 : "r"(a[0]), "r"(a[1]), "r"(a[2]), "r"(a[3]), "r"(b[0]), "r"(b[1]));
}
__device__ __forceinline__ void cpasync16(uint32_t saddr, const void* gptr) {
    asm volatile("cp.async.ca.shared.global [%0], [%1], 16;" :: "r"(saddr), "l"(gptr) : "memory");
}

// smem layout for main_kernel (dynamic), 2 stages
#define OFF_SH(st)  ((st)*16384)            // [128 pix][64 ci] fp16 swizzled
#define OFF_WH(st)  (32768 + (st)*8192)     // [64 co][64 ci] fp16 swizzled
#define OFF_IY   49152                       // 9*128 floats
#define OFF_SUMS 53760                       // 32 floats
#define SMEM_BYTES 53888

// smem layout for conv1g (dynamic): 3 S tiles of 130 pixel-rows + 9 W tiles
#define C1S(dy)  ((dy)*16640)               // [130 pix][64 ci] fp16 swizzled
#define C1W(k)   (49920 + (k)*2048)         // [16 co][64 ci] fp16 swizzled
#define C1_SMEM  68352

// ---------------- kernel 1: x NCHW fp32 -> NHWC fp16 (smem transpose) ----------------
__global__ void xprep_kernel(const float* __restrict__ x) {
    int y = blockIdx.x, b = blockIdx.y;
    int t = threadIdx.x;
    __shared__ __half xs[256*66];
    const float* xb = x + (size_t)b*CIN*HW;
#pragma unroll 4
    for (int ci = 0; ci < 64; ci++) {
        float v = __ldg(xb + ((size_t)ci*HH + y)*WW + t);
        xs[t*66 + ci] = __float2half(v);
    }
    __syncthreads();
    char* dst = (char*)(g_xh + ((size_t)b*HW + (size_t)y*WW)*64);
#pragma unroll
    for (int j = 0; j < 8; j++) {
        int c = t + 256*j;
        int w = c >> 3, cig = c & 7;
        const uint32_t* src = (const uint32_t*)&xs[w*66];   // 4B-aligned
        uint4 v;
        v.x = src[cig*4 + 0];
        v.y = src[cig*4 + 1];
        v.z = src[cig*4 + 2];
        v.w = src[cig*4 + 3];
        *(uint4*)(dst + (size_t)c*16) = v;
    }
}

// ---------------- kernel 2a: w_dsc -> fp16, [k][64co][64ci] swizzled ----------------
__global__ void wprep_kernel(const float* __restrict__ wdsc) {
    int lin = blockIdx.x*256 + threadIdx.x;       // 9*64*64
    if (lin >= KK*64*64) return;
    int ci = lin & 63, co = (lin >> 6) & 63, k = lin >> 12;
    float v = wdsc[((size_t)(co*64 + ci))*KK + k];
    uint32_t off = (uint32_t)(co*128 + ci*2);
    uint32_t sw = off ^ ((off >> 3) & 0x70);
    *(__half*)((char*)g_wh + (size_t)k*8192 + sw) = __float2half(v);
}

// ---------------- kernel 2b: w_off -> fp16, [k][16co][64ci] swizzled (co>=10 zero) ----------------
__global__ void wprepc1_kernel(const float* __restrict__ woff) {
    int lin = blockIdx.x*256 + threadIdx.x;       // 9*16*64
    if (lin >= KK*16*64) return;
    int ci = lin & 63, co = (lin >> 6) & 15, k = lin >> 10;
    float v = (co < OC1) ? woff[((size_t)(co*64 + ci))*9 + k] : 0.f;
    uint32_t off = (uint32_t)(co*128 + ci*2);
    uint32_t sw = off ^ ((off >> 3) & 0x70);
    *(__half*)((char*)g_wc1 + (size_t)k*2048 + sw) = __float2half(v);
}

// ---------------- kernel 3: 3x3 offset conv via mma, row-shared S tiles ----------------
// 3 S tiles (dy = -1,0,+1), 130 pixels each; tap (dy,dx) = ldmatrix row offset +dx+1.
// OOB y-taps skipped exactly (zero input contributes nothing).
__global__ void __launch_bounds__(256, 3)
conv1g_kernel(const float* __restrict__ b_off) {
    extern __shared__ __align__(16) char smem[];
    __shared__ float sums20[20];
    uint32_t sb = smem_u32(smem);

    int t = threadIdx.x, lane = t & 31, wid = t >> 5;
    int b = blockIdx.z, h = blockIdx.y, w0 = blockIdx.x * 128;
    if (t < 20) sums20[t] = 0.f;

    const char* xhb = (const char*)(g_xh + (size_t)b*HW*64);

    // copy all 9 W tiles (contiguous 18432 B, swizzle preserved)
    for (int i = t; i < 1152; i += 256)
        ((uint4*)(smem + C1W(0)))[i] = ((const uint4*)g_wc1)[i];

    // load 3 S tiles of 130 pixel rows
    {
        int r = t >> 3, cig = t & 7;
#pragma unroll
        for (int dy = 0; dy < 3; dy++) {
            int y = h + dy - 1;
            bool yok = (y >= 0 && y < HH);
#pragma unroll
            for (int g = 0; g < 5; g++) {
                int row = r + g*32;
                if (row >= 130) break;
                int pix = w0 - 1 + row;
                uint4 v = make_uint4(0u, 0u, 0u, 0u);
                if (yok && pix >= 0 && pix < WW) {
                    uint32_t o = (((uint32_t)y << 8) + (uint32_t)pix) << 7;
                    v = __ldg((const uint4*)(xhb + o + (cig << 4)));
                }
                uint32_t off = (uint32_t)(row*128 + (cig << 4));
                uint32_t sw = off ^ ((off >> 3) & 0x70);
                *(uint4*)(smem + C1S(dy) + sw) = v;
            }
        }
    }
    __syncthreads();

    float acc[2][4];
#pragma unroll
    for (int i = 0; i < 2; i++)
#pragma unroll
        for (int j = 0; j < 4; j++) acc[i][j] = 0.f;

#pragma unroll 1
    for (int k = 0; k < KK; k++) {
        int dy = k / 3, dxm = k % 3;        // smem row base offset = dxm (= dx+1)
        int y = h + dy - 1;
        if (y < 0 || y >= HH) continue;     // zero-padding: exact skip
        uint32_t soff = C1S(dy), woff = C1W(k);
#pragma unroll
        for (int kt = 0; kt < 4; kt++) {
            uint32_t af[4];
            {
                uint32_t row = (uint32_t)(lane & 15);
                uint32_t c16 = (uint32_t)(kt*2 + (lane >> 4));
                uint32_t off = row*128 + c16*16;
                uint32_t sw = off ^ ((off >> 3) & 0x70);
                ldsm_x4(af, sb + woff + sw);
            }
#pragma unroll
            for (int nt = 0; nt < 2; nt++) {
                uint32_t bf[2];
                uint32_t row = (uint32_t)(wid*16 + nt*8 + (lane & 7) + dxm);
                uint32_t c16 = (uint32_t)(kt*2 + ((lane >> 3) & 1));
                uint32_t off = row*128 + c16*16;
                uint32_t sw = off ^ ((off >> 3) & 0x70);
                ldsm_x2(bf, sb + soff + sw);
                mma16816h(acc[nt], af, bf);
            }
        }
    }

    // epilogue: bias, store g_off (co<10), GN partials
    {
        int q = lane >> 2;                 // co row 0..7 (and q+8)
        int pp = (lane & 3) * 2;
        float b0 = (q < OC1) ? __ldg(b_off + q) : 0.f;
        float b1 = (q + 8 < OC1) ? __ldg(b_off + q + 8) : 0.f;
        float s0 = 0.f, q0 = 0.f, s1 = 0.f, q1 = 0.f;
#pragma unroll
        for (int nt = 0; nt < 2; nt++) {
            int pix = wid*16 + nt*8 + pp;
            float v0 = acc[nt][0] + b0;
            float v1 = acc[nt][1] + b0;
            float v2 = acc[nt][2] + b1;
            float v3 = acc[nt][3] + b1;
            if (q < OC1) {
                *(float2*)&g_off[((size_t)(b*OC1 + q)*HH + h)*WW + w0 + pix] = make_float2(v0, v1);
                s0 += v0 + v1; q0 += v0*v0 + v1*v1;
            }
            if (q + 8 < OC1) {
                *(float2*)&g_off[((size_t)(b*OC1 + q + 8)*HH + h)*WW + w0 + pix] = make_float2(v2, v3);
                s1 += v2 + v3; q1 += v2*v2 + v3*v3;
            }
        }
#pragma unroll
        for (int m = 1; m <= 2; m <<= 1) {
            s0 += __shfl_xor_sync(0xffffffff, s0, m);
            q0 += __shfl_xor_sync(0xffffffff, q0, m);
            s1 += __shfl_xor_sync(0xffffffff, s1, m);
            q1 += __shfl_xor_sync(0xffffffff, q1, m);
        }
        if ((lane & 3) == 0) {
            if (q < OC1)     { atomicAdd(&sums20[q*2], s0);       atomicAdd(&sums20[q*2+1], q0); }
            if (q + 8 < OC1) { atomicAdd(&sums20[(q+8)*2], s1);   atomicAdd(&sums20[(q+8)*2+1], q1); }
        }
    }
    __syncthreads();
    if (t < 20) {
        int blk = blockIdx.x + 2*h;    // 0..511
        g_offpart[((size_t)(b*512) + blk)*20 + t] = sums20[t];
    }
}

// ---------------- kernel 4: reduce offset GN partials ----------------
__global__ void offstats_kernel() {
    int b = blockIdx.x / 5, g = blockIdx.x % 5;
    int t = threadIdx.x;
    float s = 0.f, q = 0.f;
    for (int i = t; i < 512; i += 256) {
        const float* p = g_offpart + ((size_t)(b*512) + i)*20;
        s += p[(2*g)*2]   + p[(2*g+1)*2];
        q += p[(2*g)*2+1] + p[(2*g+1)*2+1];
    }
    __shared__ float rs[256], rq[256];
    rs[t] = s; rq[t] = q; __syncthreads();
    for (int o = 128; o > 0; o >>= 1) {
        if (t < o) { rs[t] += rs[t+o]; rq[t] += rq[t+o]; }
        __syncthreads();
    }
    if (t == 0) {
        float n = (float)(2*HW);
        float mean = rs[0] / n;
        float var = rq[0] / n - mean*mean;
        g_offstats[(b*5+g)*2]   = mean;
        g_offstats[(b*5+g)*2+1] = rsqrtf(var + 1e-5f);
    }
}

// ---------------- kernel 5: pipelined coords + NHWC sampling + fp16 mma.sync GEMM ----------------
__global__ void __launch_bounds__(256, 3)
main_kernel(const float* __restrict__ x,
            const float* __restrict__ gno_w, const float* __restrict__ gno_b,
            const float* __restrict__ b_dsc,
            float* __restrict__ out) {
    extern __shared__ __align__(16) char smem[];
    uint32_t sb = smem_u32(smem);
    float* iy_sh = (float*)(smem + OFF_IY);
    float* sums  = (float*)(smem + OFF_SUMS);

    int t = threadIdx.x, lane = t & 31, wid = t >> 5;
    int b = blockIdx.z, h = blockIdx.y, w0 = blockIdx.x * 128;
    if (t < 32) sums[t] = 0.f;

    // Phase 0: GN+tanh, outward cumsum, clamped iy for 128 pixels x 9 taps
    if (t < 128) {
        int p = t, wg = w0 + p;
        float v[9];
#pragma unroll
        for (int c = 0; c < 9; c++) {
            float raw = g_off[((size_t)(b*OC1 + c)*HH + h)*WW + wg];
            int g = c >> 1;
            float mean = g_offstats[(b*5+g)*2];
            float rstd = g_offstats[(b*5+g)*2+1];
            v[c] = tanhf((raw - mean)*rstd*gno_w[c] + gno_b[c]);
        }
        float cum[9];
        cum[4] = 0.f;
        cum[3] = v[3]; cum[2] = cum[3]+v[2]; cum[1] = cum[2]+v[1]; cum[0] = cum[1]+v[0];
        cum[5] = v[5]; cum[6] = cum[5]+v[6]; cum[7] = cum[6]+v[7]; cum[8] = cum[7]+v[8];
#pragma unroll
        for (int k = 0; k < 9; k++)
            iy_sh[k*128 + p] = fminf(fmaxf((float)h + cum[k], 0.f), 255.f);
    }

    const char* xhb = (const char*)(g_xh + (size_t)b*HW*64);
    int wm = wid & 1, wn = wid >> 1;     // mma warp tiling
    int cig = t & 7;                      // sampling: 8-ci group (16B)

    float acc[2][4][4];
#pragma unroll
    for (int i = 0; i < 2; i++)
#pragma unroll
        for (int j = 0; j < 4; j++)
#pragma unroll
            for (int l = 0; l < 4; l++) acc[i][j][l] = 0.f;

    auto item_load = [&](int k, int g, uint4& a, uint4& c, float& wy) {
        int pix = (t >> 3) + g*32;
        float iy = iy_sh[k*128 + pix];
        float y0f = floorf(iy);
        wy = iy - y0f;
        int y0 = (int)y0f;
        int y1 = min(y0 + 1, 255);
        int ix = min(max(w0 + pix + k - 4, 0), 255);
        uint32_t o0 = (((uint32_t)y0 << 8) + (uint32_t)ix) << 7;
        uint32_t o1 = (((uint32_t)y1 << 8) + (uint32_t)ix) << 7;
        a = __ldg((const uint4*)(xhb + o0 + (cig << 4)));
        c = __ldg((const uint4*)(xhb + o1 + (cig << 4)));
    };
    auto item_store = [&](int g, uint32_t bufoff, uint4 a, uint4 c, float wy) {
        int pix = (t >> 3) + g*32;
        uint4 r;
        const uint32_t* ap = (const uint32_t*)&a;
        const uint32_t* cp = (const uint32_t*)&c;
        uint32_t* rp = (uint32_t*)&r;
#pragma unroll
        for (int j = 0; j < 4; j++) {
            __half2 ah, ch;
            memcpy(&ah, ap + j, 4); memcpy(&ch, cp + j, 4);
            float2 fa = __half22float2(ah), fc = __half22float2(ch);
            float2 f;
            f.x = fmaf(fc.x - fa.x, wy, fa.x);
            f.y = fmaf(fc.y - fa.y, wy, fa.y);
            __half2 hr = __floats2half2_rn(f.x, f.y);
            memcpy(rp + j, &hr, 4);
        }
        uint32_t off = (uint32_t)(pix*128 + (cig << 4));
        uint32_t sw = off ^ ((off >> 3) & 0x70);
        *(uint4*)(smem + bufoff + sw) = r;
    };
    auto wcopy = [&](int k, uint32_t bufoff) {
        const char* wsrc = (const char*)g_wh + (size_t)k*8192 + t*32;
        cpasync16(sb + bufoff + t*32,      wsrc);
        cpasync16(sb + bufoff + t*32 + 16, wsrc + 16);
        asm volatile("cp.async.commit_group;" ::: "memory");
    };
    auto mma_kt = [&](int kt, uint32_t soff, uint32_t woff) {
        uint32_t af[2][4];
#pragma unroll
        for (int mt = 0; mt < 2; mt++) {
            uint32_t row = (uint32_t)(wm*32 + mt*16 + (lane & 15));
            uint32_t c16 = (uint32_t)(kt*2 + (lane >> 4));
            uint32_t off = row*128 + c16*16;
            uint32_t sw = off ^ ((off >> 3) & 0x70);
            ldsm_x4(af[mt], sb + woff + sw);
        }
        uint32_t bf[4][2];
#pragma unroll
        for (int nt = 0; nt < 4; nt++) {
            uint32_t row = (uint32_t)(wn*32 + nt*8 + (lane & 7));
            uint32_t c16 = (uint32_t)(kt*2 + ((lane >> 3) & 1));
            uint32_t off = row*128 + c16*16;
            uint32_t sw = off ^ ((off >> 3) & 0x70);
            ldsm_x2(bf[nt], sb + soff + sw);
        }
#pragma unroll
        for (int mt = 0; mt < 2; mt++)
#pragma unroll
            for (int nt = 0; nt < 4; nt++)
                mma16816h(acc[mt][nt], af[mt], bf[nt]);
    };

    // prologue
    wcopy(0, OFF_WH(0));
    __syncthreads();
#pragma unroll
    for (int g = 0; g < 4; g++) {
        uint4 a, c; float wy;
        item_load(0, g, a, c, wy);
        item_store(g, OFF_SH(0), a, c, wy);
    }
    asm volatile("cp.async.wait_group 0;" ::: "memory");
    __syncthreads();

#pragma unroll 1
    for (int k = 0; k < KK; k++) {
        int st = k & 1, ns = st ^ 1;
        bool pf = (k < KK-1);
        uint32_t soff = OFF_SH(st), woff = OFF_WH(st);

        if (pf) wcopy(k+1, OFF_WH(ns));

#pragma unroll
        for (int g = 0; g < 4; g++) {
            uint4 a, c; float wy = 0.f;
            if (pf) item_load(k+1, g, a, c, wy);
            mma_kt(g, soff, woff);
            if (pf) item_store(g, OFF_SH(ns), a, c, wy);
        }

        if (pf) { asm volatile("cp.async.wait_group 0;" ::: "memory"); }
        __syncthreads();
    }

    // epilogue: bias, store, GN partial sums
    {
        int q = lane >> 2;
        int pp = (lane & 3) * 2;
        float s_l[2][2] = {{0.f,0.f},{0.f,0.f}}, q_l[2][2] = {{0.f,0.f},{0.f,0.f}};
#pragma unroll
        for (int mt = 0; mt < 2; mt++) {
            int cog = wm*32 + mt*16 + q;
            float b0 = __ldg(b_dsc + cog);
            float b1 = __ldg(b_dsc + cog + 8);
#pragma unroll
            for (int nt = 0; nt < 4; nt++) {
                int pix = wn*32 + nt*8 + pp;
                float v0 = acc[mt][nt][0] + b0;
                float v1 = acc[mt][nt][1] + b0;
                float v2 = acc[mt][nt][2] + b1;
                float v3 = acc[mt][nt][3] + b1;
                *(float2*)&out[((size_t)(b*64 + cog)*HH + h)*WW + w0 + pix]     = make_float2(v0, v1);
                *(float2*)&out[((size_t)(b*64 + cog + 8)*HH + h)*WW + w0 + pix] = make_float2(v2, v3);
                s_l[mt][0] += v0 + v1; q_l[mt][0] += v0*v0 + v1*v1;
                s_l[mt][1] += v2 + v3; q_l[mt][1] += v2*v2 + v3*v3;
            }
        }
#pragma unroll
        for (int mt = 0; mt < 2; mt++)
#pragma unroll
            for (int hf = 0; hf < 2; hf++) {
#pragma unroll
                for (int m = 1; m <= 2; m <<= 1) {
                    s_l[mt][hf] += __shfl_xor_sync(0xffffffff, s_l[mt][hf], m);
                    q_l[mt][hf] += __shfl_xor_sync(0xffffffff, q_l[mt][hf], m);
                }
                if ((lane & 3) == 0) {
                    int grp = (wm*32 + mt*16 + hf*8 + q) >> 2;
                    atomicAdd(&sums[2*grp],   s_l[mt][hf]);
                    atomicAdd(&sums[2*grp+1], q_l[mt][hf]);
                }
            }
    }
    __syncthreads();
    if (t < 32) {
        int bw = blockIdx.x + 2*h;
        g_part[((size_t)(b*512 + bw)*16 + (t >> 1))*2 + (t & 1)] = sums[t];
    }
}

// ---------------- kernel 6: reduce out-GN partials ----------------
__global__ void outstats_kernel() {
    int b = blockIdx.x >> 4, g = blockIdx.x & 15;
    int t = threadIdx.x;
    float s = 0.f, q = 0.f;
    for (int i = t; i < 512; i += 256) {
        size_t idx = ((size_t)(b*512 + i)*16 + g)*2;
        s += g_part[idx];
        q += g_part[idx + 1];
    }
    __shared__ float rs[256], rq[256];
    rs[t] = s; rq[t] = q; __syncthreads();
    for (int o = 128; o > 0; o >>= 1) {
        if (t < o) { rs[t] += rs[t+o]; rq[t] += rq[t+o]; }
        __syncthreads();
    }
    if (t == 0) {
        float n = 4.f * HW;
        float mean = rs[0] / n;
        float var = rq[0] / n - mean*mean;
        g_outmr[(b*16+g)*2]   = mean;
        g_outmr[(b*16+g)*2+1] = rsqrtf(var + 1e-5f);
    }
}

// ---------------- kernel 7: apply GN + ReLU ----------------
__global__ void apply_kernel(float* __restrict__ out,
                             const float* __restrict__ gn_w,
                             const float* __restrict__ gn_b) {
    int idx4 = blockIdx.x*blockDim.x + threadIdx.x;
    size_t base = (size_t)idx4 * 4;
    int co = (int)((base >> 16) & 63);
    int b  = (int)(base >> 22);
    int g  = co >> 2;
    float mean = g_outmr[(b*16+g)*2];
    float rstd = g_outmr[(b*16+g)*2+1];
    float sc = rstd * gn_w[co];
    float sh = gn_b[co] - mean * sc;
    float4 v = *(float4*)&out[base];
    v.x = fmaxf(fmaf(v.x, sc, sh), 0.f);
    v.y = fmaxf(fmaf(v.y, sc, sh), 0.f);
    v.z = fmaxf(fmaf(v.z, sc, sh), 0.f);
    v.w = fmaxf(fmaf(v.w, sc, sh), 0.f);
    *(float4*)&out[base] = v;
}

// ---------------- launch ----------------
extern "C" void kernel_launch(void* const* d_in, const int* in_sizes, int n_in,
                              void* d_out, int out_size) {
    const float* x     = (const float*)d_in[0];
    const float* w_off = (const float*)d_in[1];
    const float* b_off = (const float*)d_in[2];
    const float* gno_w = (const float*)d_in[3];
    const float* gno_b = (const float*)d_in[4];
    const float* w_dsc = (const float*)d_in[5];
    const float* b_dsc = (const float*)d_in[6];
    const float* gn_w  = (const float*)d_in[7];
    const float* gn_b  = (const float*)d_in[8];
    float* out = (float*)d_out;

    cudaFuncSetAttribute(main_kernel, cudaFuncAttributeMaxDynamicSharedMemorySize, SMEM_BYTES);
    cudaFuncSetAttribute(conv1g_kernel, cudaFuncAttributeMaxDynamicSharedMemorySize, C1_SMEM);

    xprep_kernel<<<dim3(HH, BN), 256>>>(x);
    wprep_kernel<<<(KK*64*64 + 255)/256, 256>>>(w_dsc);
    wprepc1_kernel<<<(KK*16*64 + 255)/256, 256>>>(w_off);
    conv1g_kernel<<<dim3(2, HH, BN), 256, C1_SMEM>>>(b_off);
    offstats_kernel<<<BN*5, 256>>>();
    main_kernel<<<dim3(2, HH, BN), 256, SMEM_BYTES>>>(x, gno_w, gno_b, b_dsc, out);
    outstats_kernel<<<BN*16, 256>>>();
    apply_kernel<<<4096, 512>>>(out, gn_w, gn_b);
}

// round 16
// speedup vs baseline: 4.3245x; 1.0430x over previous
#include <cuda_runtime.h>
#include <cuda_bf16.h>
#include <cuda_fp16.h>
#include <cstdint>
#include <cstring>

#define BN 2
#define CIN 64
#define HH 256
#define WW 256
#define KK 9
#define OC1 10
#define HW (HH*WW)

// ---------------- scratch ----------------
__device__ float g_off[BN*OC1*HW];
__device__ float g_offpart[BN*256*20];    // per-conv1-block (sum,sumsq) x 10 ch
__device__ float g_offstats[BN*5*2];
__device__ __align__(16) __half g_wh[KK*4096];         // [k][swizzled 64co x 64ci] fp16 (dsc conv)
__device__ __align__(16) __half g_wc1[KK*1024];        // [k][swizzled 16co x 64ci] fp16 (offset conv)
__device__ __align__(16) __half g_xh[(size_t)BN*HW*64]; // NHWC fp16: [b][y][x][ci]
__device__ float g_part[BN*512*16*2];
__device__ float g_outmr[BN*16*2];

// ---------------- mma helpers (baseline PTX, no 'a' features) ----------------
__device__ __forceinline__ uint32_t smem_u32(const void* p) {
    uint32_t a;
    asm("{ .reg .u64 t; cvta.to.shared.u64 t, %1; cvt.u32.u64 %0, t; }" : "=r"(a) : "l"(p));
    return a;
}
__device__ __forceinline__ void ldsm_x4(uint32_t* r, uint32_t addr) {
    asm volatile("ldmatrix.sync.aligned.m8n8.x4.shared.b16 {%0,%1,%2,%3}, [%4];"
                 : "=r"(r[0]), "=r"(r[1]), "=r"(r[2]), "=r"(r[3]) : "r"(addr));
}
__device__ __forceinline__ void ldsm_x2(uint32_t* r, uint32_t addr) {
    asm volatile("ldmatrix.sync.aligned.m8n8.x2.shared.b16 {%0,%1}, [%2];"
                 : "=r"(r[0]), "=r"(r[1]) : "r"(addr));
}
__device__ __forceinline__ void mma16816h(float* d, const uint32_t* a, const uint32_t* b) {
    asm volatile("mma.sync.aligned.m16n8k16.row.col.f32.f16.f16.f32 "
                 "{%0,%1,%2,%3}, {%4,%5,%6,%7}, {%8,%9}, {%0,%1,%2,%3};"
                 : "+f"(d[0]), "+f"(d[1]), "+f"(d[2]), "+f"(d[3])
                 : "r"(a[0]), "r"(a[1]), "r"(a[2]), "r"(a[3]), "r"(b[0]), "r"(b[1]));
}
__device__ __forceinline__ void cpasync16(uint32_t saddr, const void* gptr) {
    asm volatile("cp.async.ca.shared.global [%0], [%1], 16;" :: "r"(saddr), "l"(gptr) : "memory");
}

// smem layout for main_kernel (dynamic), 2 stages
#define OFF_SH(st)  ((st)*16384)            // [128 pix][64 ci] fp16 swizzled
#define OFF_WH(st)  (32768 + (st)*8192)     // [64 co][64 ci] fp16 swizzled
#define OFF_IY   49152                       // 9*128 floats
#define OFF_SUMS 53760                       // 32 floats
#define SMEM_BYTES 53888

// smem layout for conv1g (dynamic): 4 S tiles of 130 pixel-rows + 9 W tiles
#define C1S(i)   ((i)*16640)                // [130 pix][64 ci] fp16 swizzled, i=0..3
#define C1W(k)   (66560 + (k)*2048)         // [16 co][64 ci] fp16 swizzled
#define C1_SMEM  84992

// ---------------- kernel 1: x NCHW fp32 -> NHWC fp16 (smem transpose) ----------------
__global__ void xprep_kernel(const float* __restrict__ x) {
    int y = blockIdx.x, b = blockIdx.y;
    int t = threadIdx.x;
    __shared__ __half xs[256*66];
    const float* xb = x + (size_t)b*CIN*HW;
#pragma unroll 4
    for (int ci = 0; ci < 64; ci++) {
        float v = __ldg(xb + ((size_t)ci*HH + y)*WW + t);
        xs[t*66 + ci] = __float2half(v);
    }
    __syncthreads();
    char* dst = (char*)(g_xh + ((size_t)b*HW + (size_t)y*WW)*64);
#pragma unroll
    for (int j = 0; j < 8; j++) {
        int c = t + 256*j;
        int w = c >> 3, cig = c & 7;
        const uint32_t* src = (const uint32_t*)&xs[w*66];   // 4B-aligned
        uint4 v;
        v.x = src[cig*4 + 0];
        v.y = src[cig*4 + 1];
        v.z = src[cig*4 + 2];
        v.w = src[cig*4 + 3];
        *(uint4*)(dst + (size_t)c*16) = v;
    }
}

// ---------------- kernel 2a: w_dsc -> fp16, [k][64co][64ci] swizzled ----------------
__global__ void wprep_kernel(const float* __restrict__ wdsc) {
    int lin = blockIdx.x*256 + threadIdx.x;       // 9*64*64
    if (lin >= KK*64*64) return;
    int ci = lin & 63, co = (lin >> 6) & 63, k = lin >> 12;
    float v = wdsc[((size_t)(co*64 + ci))*KK + k];
    uint32_t off = (uint32_t)(co*128 + ci*2);
    uint32_t sw = off ^ ((off >> 3) & 0x70);
    *(__half*)((char*)g_wh + (size_t)k*8192 + sw) = __float2half(v);
}

// ---------------- kernel 2b: w_off -> fp16, [k][16co][64ci] swizzled (co>=10 zero) ----------------
__global__ void wprepc1_kernel(const float* __restrict__ woff) {
    int lin = blockIdx.x*256 + threadIdx.x;       // 9*16*64
    if (lin >= KK*16*64) return;
    int ci = lin & 63, co = (lin >> 6) & 15, k = lin >> 10;
    float v = (co < OC1) ? woff[((size_t)(co*64 + ci))*9 + k] : 0.f;
    uint32_t off = (uint32_t)(co*128 + ci*2);
    uint32_t sw = off ^ ((off >> 3) & 0x70);
    *(__half*)((char*)g_wc1 + (size_t)k*2048 + sw) = __float2half(v);
}

// ---------------- kernel 3: 3x3 offset conv via mma, 2 output rows per CTA ----------------
// 4 S tiles (y = h0-1 .. h0+2), 130 pixels each; out-row r uses tiles r..r+2.
// Tap (dy,dx) = tile r+dy, ldmatrix row offset +dx+1. OOB y-taps skipped exactly.
__global__ void __launch_bounds__(256, 2)
conv1g_kernel(const float* __restrict__ b_off) {
    extern __shared__ __align__(16) char smem[];
    __shared__ float sums20[20];
    uint32_t sb = smem_u32(smem);

    int t = threadIdx.x, lane = t & 31, wid = t >> 5;
    int b = blockIdx.z, h0 = blockIdx.y * 2, w0 = blockIdx.x * 128;
    if (t < 20) sums20[t] = 0.f;

    const char* xhb = (const char*)(g_xh + (size_t)b*HW*64);

    // copy all 9 W tiles (contiguous 18432 B, swizzle preserved)
    for (int i = t; i < 1152; i += 256)
        ((uint4*)(smem + C1W(0)))[i] = ((const uint4*)g_wc1)[i];

    // load 4 S tiles of 130 pixel rows (y = h0-1 .. h0+2)
    {
        int r = t >> 3, cig = t & 7;
#pragma unroll
        for (int ty = 0; ty < 4; ty++) {
            int y = h0 + ty - 1;
            bool yok = (y >= 0 && y < HH);
#pragma unroll
            for (int g = 0; g < 5; g++) {
                int row = r + g*32;
                if (row >= 130) break;
                int pix = w0 - 1 + row;
                uint4 v = make_uint4(0u, 0u, 0u, 0u);
                if (yok && pix >= 0 && pix < WW) {
                    uint32_t o = (((uint32_t)y << 8) + (uint32_t)pix) << 7;
                    v = __ldg((const uint4*)(xhb + o + (cig << 4)));
                }
                uint32_t off = (uint32_t)(row*128 + (cig << 4));
                uint32_t sw = off ^ ((off >> 3) & 0x70);
                *(uint4*)(smem + C1S(ty) + sw) = v;
            }
        }
    }
    __syncthreads();

    float acc[2][2][4];   // [row][nt][frag]
#pragma unroll
    for (int r = 0; r < 2; r++)
#pragma unroll
        for (int i = 0; i < 2; i++)
#pragma unroll
            for (int j = 0; j < 4; j++) acc[r][i][j] = 0.f;

#pragma unroll 1
    for (int k = 0; k < KK; k++) {
        int dy = k / 3, dxm = k % 3;        // smem row base offset = dxm (= dx+1)
        uint32_t woff = C1W(k);
#pragma unroll
        for (int kt = 0; kt < 4; kt++) {
            uint32_t af[4];
            {
                uint32_t row = (uint32_t)(lane & 15);
                uint32_t c16 = (uint32_t)(kt*2 + (lane >> 4));
                uint32_t off = row*128 + c16*16;
                uint32_t sw = off ^ ((off >> 3) & 0x70);
                ldsm_x4(af, sb + woff + sw);
            }
#pragma unroll
            for (int r = 0; r < 2; r++) {
                int y = h0 + r + dy - 1;
                if (y < 0 || y >= HH) continue;   // zero-padding: exact skip
                uint32_t soff = C1S(r + dy);
#pragma unroll
                for (int nt = 0; nt < 2; nt++) {
                    uint32_t bf[2];
                    uint32_t row = (uint32_t)(wid*16 + nt*8 + (lane & 7) + dxm);
                    uint32_t c16 = (uint32_t)(kt*2 + ((lane >> 3) & 1));
                    uint32_t off = row*128 + c16*16;
                    uint32_t sw = off ^ ((off >> 3) & 0x70);
                    ldsm_x2(bf, sb + soff + sw);
                    mma16816h(acc[r][nt], af, bf);
                }
            }
        }
    }

    // epilogue: bias, store g_off (co<10), GN partials (both rows)
    {
        int q = lane >> 2;                 // co row 0..7 (and q+8)
        int pp = (lane & 3) * 2;
        float b0 = (q < OC1) ? __ldg(b_off + q) : 0.f;
        float b1 = (q + 8 < OC1) ? __ldg(b_off + q + 8) : 0.f;
        float s0 = 0.f, q0 = 0.f, s1 = 0.f, q1 = 0.f;
#pragma unroll
        for (int r = 0; r < 2; r++) {
            int h = h0 + r;
#pragma unroll
            for (int nt = 0; nt < 2; nt++) {
                int pix = wid*16 + nt*8 + pp;
                float v0 = acc[r][nt][0] + b0;
                float v1 = acc[r][nt][1] + b0;
                float v2 = acc[r][nt][2] + b1;
                float v3 = acc[r][nt][3] + b1;
                if (q < OC1) {
                    *(float2*)&g_off[((size_t)(b*OC1 + q)*HH + h)*WW + w0 + pix] = make_float2(v0, v1);
                    s0 += v0 + v1; q0 += v0*v0 + v1*v1;
                }
                if (q + 8 < OC1) {
                    *(float2*)&g_off[((size_t)(b*OC1 + q + 8)*HH + h)*WW + w0 + pix] = make_float2(v2, v3);
                    s1 += v2 + v3; q1 += v2*v2 + v3*v3;
                }
            }
        }
#pragma unroll
        for (int m = 1; m <= 2; m <<= 1) {
            s0 += __shfl_xor_sync(0xffffffff, s0, m);
            q0 += __shfl_xor_sync(0xffffffff, q0, m);
            s1 += __shfl_xor_sync(0xffffffff, s1, m);
            q1 += __shfl_xor_sync(0xffffffff, q1, m);
        }
        if ((lane & 3) == 0) {
            if (q < OC1)     { atomicAdd(&sums20[q*2], s0);       atomicAdd(&sums20[q*2+1], q0); }
            if (q + 8 < OC1) { atomicAdd(&sums20[(q+8)*2], s1);   atomicAdd(&sums20[(q+8)*2+1], q1); }
        }
    }
    __syncthreads();
    if (t < 20) {
        int blk = blockIdx.x + 2*blockIdx.y;    // 0..255
        g_offpart[((size_t)(b*256) + blk)*20 + t] = sums20[t];
    }
}

// ---------------- kernel 4: reduce offset GN partials ----------------
__global__ void offstats_kernel() {
    int b = blockIdx.x / 5, g = blockIdx.x % 5;
    int t = threadIdx.x;
    float s = 0.f, q = 0.f;
    if (t < 256) {
        const float* p = g_offpart + ((size_t)(b*256) + t)*20;
        s = p[(2*g)*2]   + p[(2*g+1)*2];
        q = p[(2*g)*2+1] + p[(2*g+1)*2+1];
    }
    __shared__ float rs[256], rq[256];
    rs[t] = s; rq[t] = q; __syncthreads();
    for (int o = 128; o > 0; o >>= 1) {
        if (t < o) { rs[t] += rs[t+o]; rq[t] += rq[t+o]; }
        __syncthreads();
    }
    if (t == 0) {
        float n = (float)(2*HW);
        float mean = rs[0] / n;
        float var = rq[0] / n - mean*mean;
        g_offstats[(b*5+g)*2]   = mean;
        g_offstats[(b*5+g)*2+1] = rsqrtf(var + 1e-5f);
    }
}

// ---------------- kernel 5: pipelined coords + NHWC sampling + fp16 mma.sync GEMM ----------------
__global__ void __launch_bounds__(256, 3)
main_kernel(const float* __restrict__ x,
            const float* __restrict__ gno_w, const float* __restrict__ gno_b,
            const float* __restrict__ b_dsc,
            float* __restrict__ out) {
    extern __shared__ __align__(16) char smem[];
    uint32_t sb = smem_u32(smem);
    float* iy_sh = (float*)(smem + OFF_IY);
    float* sums  = (float*)(smem + OFF_SUMS);

    int t = threadIdx.x, lane = t & 31, wid = t >> 5;
    int b = blockIdx.z, h = blockIdx.y, w0 = blockIdx.x * 128;
    if (t < 32) sums[t] = 0.f;

    // Phase 0: GN+tanh, outward cumsum, clamped iy for 128 pixels x 9 taps
    if (t < 128) {
        int p = t, wg = w0 + p;
        float v[9];
#pragma unroll
        for (int c = 0; c < 9; c++) {
            float raw = g_off[((size_t)(b*OC1 + c)*HH + h)*WW + wg];
            int g = c >> 1;
            float mean = g_offstats[(b*5+g)*2];
            float rstd = g_offstats[(b*5+g)*2+1];
            v[c] = tanhf((raw - mean)*rstd*gno_w[c] + gno_b[c]);
        }
        float cum[9];
        cum[4] = 0.f;
        cum[3] = v[3]; cum[2] = cum[3]+v[2]; cum[1] = cum[2]+v[1]; cum[0] = cum[1]+v[0];
        cum[5] = v[5]; cum[6] = cum[5]+v[6]; cum[7] = cum[6]+v[7]; cum[8] = cum[7]+v[8];
#pragma unroll
        for (int k = 0; k < 9; k++)
            iy_sh[k*128 + p] = fminf(fmaxf((float)h + cum[k], 0.f), 255.f);
    }

    const char* xhb = (const char*)(g_xh + (size_t)b*HW*64);
    int wm = wid & 1, wn = wid >> 1;     // mma warp tiling
    int cig = t & 7;                      // sampling: 8-ci group (16B)

    float acc[2][4][4];
#pragma unroll
    for (int i = 0; i < 2; i++)
#pragma unroll
        for (int j = 0; j < 4; j++)
#pragma unroll
            for (int l = 0; l < 4; l++) acc[i][j][l] = 0.f;

    auto item_load = [&](int k, int g, uint4& a, uint4& c, float& wy) {
        int pix = (t >> 3) + g*32;
        float iy = iy_sh[k*128 + pix];
        float y0f = floorf(iy);
        wy = iy - y0f;
        int y0 = (int)y0f;
        int y1 = min(y0 + 1, 255);
        int ix = min(max(w0 + pix + k - 4, 0), 255);
        uint32_t o0 = (((uint32_t)y0 << 8) + (uint32_t)ix) << 7;
        uint32_t o1 = (((uint32_t)y1 << 8) + (uint32_t)ix) << 7;
        a = __ldg((const uint4*)(xhb + o0 + (cig << 4)));
        c = __ldg((const uint4*)(xhb + o1 + (cig << 4)));
    };
    auto item_store = [&](int g, uint32_t bufoff, uint4 a, uint4 c, float wy) {
        int pix = (t >> 3) + g*32;
        uint4 r;
        const uint32_t* ap = (const uint32_t*)&a;
        const uint32_t* cp = (const uint32_t*)&c;
        uint32_t* rp = (uint32_t*)&r;
#pragma unroll
        for (int j = 0; j < 4; j++) {
            __half2 ah, ch;
            memcpy(&ah, ap + j, 4); memcpy(&ch, cp + j, 4);
            float2 fa = __half22float2(ah), fc = __half22float2(ch);
            float2 f;
            f.x = fmaf(fc.x - fa.x, wy, fa.x);
            f.y = fmaf(fc.y - fa.y, wy, fa.y);
            __half2 hr = __floats2half2_rn(f.x, f.y);
            memcpy(rp + j, &hr, 4);
        }
        uint32_t off = (uint32_t)(pix*128 + (cig << 4));
        uint32_t sw = off ^ ((off >> 3) & 0x70);
        *(uint4*)(smem + bufoff + sw) = r;
    };
    auto wcopy = [&](int k, uint32_t bufoff) {
        const char* wsrc = (const char*)g_wh + (size_t)k*8192 + t*32;
        cpasync16(sb + bufoff + t*32,      wsrc);
        cpasync16(sb + bufoff + t*32 + 16, wsrc + 16);
        asm volatile("cp.async.commit_group;" ::: "memory");
    };
    auto mma_kt = [&](int kt, uint32_t soff, uint32_t woff) {
        uint32_t af[2][4];
#pragma unroll
        for (int mt = 0; mt < 2; mt++) {
            uint32_t row = (uint32_t)(wm*32 + mt*16 + (lane & 15));
            uint32_t c16 = (uint32_t)(kt*2 + (lane >> 4));
            uint32_t off = row*128 + c16*16;
            uint32_t sw = off ^ ((off >> 3) & 0x70);
            ldsm_x4(af[mt], sb + woff + sw);
        }
        uint32_t bf[4][2];
#pragma unroll
        for (int nt = 0; nt < 4; nt++) {
            uint32_t row = (uint32_t)(wn*32 + nt*8 + (lane & 7));
            uint32_t c16 = (uint32_t)(kt*2 + ((lane >> 3) & 1));
            uint32_t off = row*128 + c16*16;
            uint32_t sw = off ^ ((off >> 3) & 0x70);
            ldsm_x2(bf[nt], sb + soff + sw);
        }
#pragma unroll
        for (int mt = 0; mt < 2; mt++)
#pragma unroll
            for (int nt = 0; nt < 4; nt++)
                mma16816h(acc[mt][nt], af[mt], bf[nt]);
    };

    // prologue
    wcopy(0, OFF_WH(0));
    __syncthreads();
#pragma unroll
    for (int g = 0; g < 4; g++) {
        uint4 a, c; float wy;
        item_load(0, g, a, c, wy);
        item_store(g, OFF_SH(0), a, c, wy);
    }
    asm volatile("cp.async.wait_group 0;" ::: "memory");
    __syncthreads();

#pragma unroll 1
    for (int k = 0; k < KK; k++) {
        int st = k & 1, ns = st ^ 1;
        bool pf = (k < KK-1);
        uint32_t soff = OFF_SH(st), woff = OFF_WH(st);

        if (pf) wcopy(k+1, OFF_WH(ns));

#pragma unroll
        for (int g = 0; g < 4; g++) {
            uint4 a, c; float wy = 0.f;
            if (pf) item_load(k+1, g, a, c, wy);
            mma_kt(g, soff, woff);
            if (pf) item_store(g, OFF_SH(ns), a, c, wy);
        }

        if (pf) { asm volatile("cp.async.wait_group 0;" ::: "memory"); }
        __syncthreads();
    }

    // epilogue: bias, store, GN partial sums
    {
        int q = lane >> 2;
        int pp = (lane & 3) * 2;
        float s_l[2][2] = {{0.f,0.f},{0.f,0.f}}, q_l[2][2] = {{0.f,0.f},{0.f,0.f}};
#pragma unroll
        for (int mt = 0; mt < 2; mt++) {
            int cog = wm*32 + mt*16 + q;
            float b0 = __ldg(b_dsc + cog);
            float b1 = __ldg(b_dsc + cog + 8);
#pragma unroll
            for (int nt = 0; nt < 4; nt++) {
                int pix = wn*32 + nt*8 + pp;
                float v0 = acc[mt][nt][0] + b0;
                float v1 = acc[mt][nt][1] + b0;
                float v2 = acc[mt][nt][2] + b1;
                float v3 = acc[mt][nt][3] + b1;
                *(float2*)&out[((size_t)(b*64 + cog)*HH + h)*WW + w0 + pix]     = make_float2(v0, v1);
                *(float2*)&out[((size_t)(b*64 + cog + 8)*HH + h)*WW + w0 + pix] = make_float2(v2, v3);
                s_l[mt][0] += v0 + v1; q_l[mt][0] += v0*v0 + v1*v1;
                s_l[mt][1] += v2 + v3; q_l[mt][1] += v2*v2 + v3*v3;
            }
        }
#pragma unroll
        for (int mt = 0; mt < 2; mt++)
#pragma unroll
            for (int hf = 0; hf < 2; hf++) {
#pragma unroll
                for (int m = 1; m <= 2; m <<= 1) {
                    s_l[mt][hf] += __shfl_xor_sync(0xffffffff, s_l[mt][hf], m);
                    q_l[mt][hf] += __shfl_xor_sync(0xffffffff, q_l[mt][hf], m);
                }
                if ((lane & 3) == 0) {
                    int grp = (wm*32 + mt*16 + hf*8 + q) >> 2;
                    atomicAdd(&sums[2*grp],   s_l[mt][hf]);
                    atomicAdd(&sums[2*grp+1], q_l[mt][hf]);
                }
            }
    }
    __syncthreads();
    if (t < 32) {
        int bw = blockIdx.x + 2*h;
        g_part[((size_t)(b*512 + bw)*16 + (t >> 1))*2 + (t & 1)] = sums[t];
    }
}

// ---------------- kernel 6: reduce out-GN partials ----------------
__global__ void outstats_kernel() {
    int b = blockIdx.x >> 4, g = blockIdx.x & 15;
    int t = threadIdx.x;
    float s = 0.f, q = 0.f;
    for (int i = t; i < 512; i += 256) {
        size_t idx = ((size_t)(b*512 + i)*16 + g)*2;
        s += g_part[idx];
        q += g_part[idx + 1];
    }
    __shared__ float rs[256], rq[256];
    rs[t] = s; rq[t] = q; __syncthreads();
    for (int o = 128; o > 0; o >>= 1) {
        if (t < o) { rs[t] += rs[t+o]; rq[t] += rq[t+o]; }
        __syncthreads();
    }
    if (t == 0) {
        float n = 4.f * HW;
        float mean = rs[0] / n;
        float var = rq[0] / n - mean*mean;
        g_outmr[(b*16+g)*2]   = mean;
        g_outmr[(b*16+g)*2+1] = rsqrtf(var + 1e-5f);
    }
}

// ---------------- kernel 7: apply GN + ReLU ----------------
__global__ void apply_kernel(float* __restrict__ out,
                             const float* __restrict__ gn_w,
                             const float* __restrict__ gn_b) {
    int idx4 = blockIdx.x*blockDim.x + threadIdx.x;
    size_t base = (size_t)idx4 * 4;
    int co = (int)((base >> 16) & 63);
    int b  = (int)(base >> 22);
    int g  = co >> 2;
    float mean = g_outmr[(b*16+g)*2];
    float rstd = g_outmr[(b*16+g)*2+1];
    float sc = rstd * gn_w[co];
    float sh = gn_b[co] - mean * sc;
    float4 v = *(float4*)&out[base];
    v.x = fmaxf(fmaf(v.x, sc, sh), 0.f);
    v.y = fmaxf(fmaf(v.y, sc, sh), 0.f);
    v.z = fmaxf(fmaf(v.z, sc, sh), 0.f);
    v.w = fmaxf(fmaf(v.w, sc, sh), 0.f);
    *(float4*)&out[base] = v;
}

// ---------------- launch ----------------
extern "C" void kernel_launch(void* const* d_in, const int* in_sizes, int n_in,
                              void* d_out, int out_size) {
    const float* x     = (const float*)d_in[0];
    const float* w_off = (const float*)d_in[1];
    const float* b_off = (const float*)d_in[2];
    const float* gno_w = (const float*)d_in[3];
    const float* gno_b = (const float*)d_in[4];
    const float* w_dsc = (const float*)d_in[5];
    const float* b_dsc = (const float*)d_in[6];
    const float* gn_w  = (const float*)d_in[7];
    const float* gn_b  = (const float*)d_in[8];
    float* out = (float*)d_out;

    cudaFuncSetAttribute(main_kernel, cudaFuncAttributeMaxDynamicSharedMemorySize, SMEM_BYTES);
    cudaFuncSetAttribute(conv1g_kernel, cudaFuncAttributeMaxDynamicSharedMemorySize, C1_SMEM);

    xprep_kernel<<<dim3(HH, BN), 256>>>(x);
    wprep_kernel<<<(KK*64*64 + 255)/256, 256>>>(w_dsc);
    wprepc1_kernel<<<(KK*16*64 + 255)/256, 256>>>(w_off);
    conv1g_kernel<<<dim3(2, HH/2, BN), 256, C1_SMEM>>>(b_off);
    offstats_kernel<<<BN*5, 256>>>();
    main_kernel<<<dim3(2, HH, BN), 256, SMEM_BYTES>>>(x, gno_w, gno_b, b_dsc, out);
    outstats_kernel<<<BN*16, 256>>>();
    apply_kernel<<<4096, 512>>>(out, gn_w, gn_b);
}